// round 13
// baseline (speedup 1.0000x reference)
#include <cuda_runtime.h>
#include <cstdint>

// ---------------------------------------------------------------------------
// MambaBlock: B=2, T=1024, DM=1024, D=2048, N=16, K=4, DTR=128
// Round 13: round-12 base + pre-rounded (RNA tf32) GEMM operands everywhere.
// Hot GEMM loops carry zero CVT: 50% (big) / 33% (dbc) MMA issue density.
// ---------------------------------------------------------------------------

#define DMv   1024
#define Dv    2048
#define Tv    1024
#define NROWS 2048
#define NSTv  16

// Scratch layout (floats)
#define OFF_H      0u          // 2048*1024   rounded
#define OFF_PROJ   2097152u    // 2048*4096   plain
#define OFF_X1C    10485760u   // 2048*2048   plain (scan)
#define OFF_DBC    14680064u   // 2048*160    delta cols rounded; B/C plain
#define OFF_DELTA  15007744u   // 2048*2048   plain (scan)
#define OFF_YMOD   19202048u   // 2048*2048   rounded
#define OFF_DBCP   23396352u   // 8*2048*160  split-K partials
#define OFF_OUTP   26017792u   // 2*2048*1024 out_proj split-K partials
#define OFF_X1CP   30212096u   // 2048*2048   rounded (dbc A)
#define OFF_WINR   34406400u   // 1024*4096   in_W rounded
#define OFF_WDBCR  38600704u   // 2048*160    dbc_W rounded
#define OFF_WDUPR  38928384u   // 128*2048    dup_W rounded
#define OFF_WOUTR  39190528u   // 2048*1024   out_W rounded
#define SCRATCH_FLOATS 41287680u

__device__ __align__(128) float g_scratch[SCRATCH_FLOATS];

__device__ __forceinline__ float silu_f(float v) {
    return v * (1.0f / (1.0f + __expf(-v)));
}
__device__ __forceinline__ float tf32r(float f) {
    unsigned u;
    asm("cvt.rna.tf32.f32 %0, %1;" : "=r"(u) : "f"(f));
    return __uint_as_float(u);
}
__device__ __forceinline__ void cp16(float* dst, const float* src, bool p) {
    unsigned d = (unsigned)__cvta_generic_to_shared(dst);
    int sz = p ? 16 : 0;
    asm volatile("cp.async.cg.shared.global [%0], [%1], 16, %2;\n"
                 :: "r"(d), "l"(src), "r"(sz));
}

// ---------------------------------------------------------------------------
// Elementwise tf32 rounding copy (weights). size % 1024 == 0.
// ---------------------------------------------------------------------------
__global__ void __launch_bounds__(256) round_k(
    const float* __restrict__ W, float* __restrict__ Wr)
{
    size_t i = ((size_t)blockIdx.x * 256 + threadIdx.x) * 4;
    float4 v = *reinterpret_cast<const float4*>(&W[i]);
    v.x = tf32r(v.x); v.y = tf32r(v.y); v.z = tf32r(v.z); v.w = tf32r(v.w);
    *reinterpret_cast<float4*>(&Wr[i]) = v;
}

// ---------------------------------------------------------------------------
// RMSNorm -> h (rounded)
// ---------------------------------------------------------------------------
__global__ void __launch_bounds__(256) rmsnorm_k(
    const float* __restrict__ x, const float* __restrict__ w, float* __restrict__ out)
{
    int row = blockIdx.x;
    const float4* xr = reinterpret_cast<const float4*>(x + (size_t)row * DMv);
    float4 v = xr[threadIdx.x];
    float s = v.x * v.x + v.y * v.y + v.z * v.z + v.w * v.w;
    #pragma unroll
    for (int o = 16; o; o >>= 1) s += __shfl_xor_sync(0xffffffffu, s, o);
    __shared__ float ws[8];
    if ((threadIdx.x & 31) == 0) ws[threadIdx.x >> 5] = s;
    __syncthreads();
    float tot = 0.f;
    #pragma unroll
    for (int i = 0; i < 8; i++) tot += ws[i];
    float scale = rsqrtf(tot * (1.0f / (float)DMv) + 1e-6f);
    float4 wv = reinterpret_cast<const float4*>(w)[threadIdx.x];
    float4 o;
    o.x = tf32r(v.x * scale * wv.x); o.y = tf32r(v.y * scale * wv.y);
    o.z = tf32r(v.z * scale * wv.z); o.w = tf32r(v.w * scale * wv.w);
    reinterpret_cast<float4*>(out + (size_t)row * DMv)[threadIdx.x] = o;
}

// ---------------------------------------------------------------------------
// Big-tile 3-stage pipelined tf32 GEMM: BM=256, BN=128, BK=32.
// Operands pre-rounded; hot loop has no CVT.
// EPI 0: +bias  1: +bias,softplus  3: raw (split-K partial)
// ---------------------------------------------------------------------------
template <int EPI>
__global__ void __launch_bounds__(256) gemm_big(
    const float* __restrict__ A, const float* __restrict__ B,
    const float* __restrict__ bias, float* __restrict__ C,
    int N, int Kd, int lda, size_t partStride)
{
    constexpr int BM = 256, BN = 128, BK = 32;
    constexpr int ASTR = BK + 4;            // 36
    constexpr int BSTR = BN + 8;            // 136
    constexpr int ASZ = BM * ASTR, BSZ = BK * BSTR, STAGE = ASZ + BSZ;

    extern __shared__ float smem[];

    int tid = threadIdx.x, lane = tid & 31, warp = tid >> 5;
    int wm = warp >> 1, wn = warp & 1;
    int bm = blockIdx.y * BM, bn = blockIdx.x * BN;
    int part = blockIdx.z;
    const float* Ap = A + (size_t)part * Kd;
    const float* Bp = B + (size_t)part * Kd * N;
    float* Cp = C + (size_t)part * partStride;

    float acc[4][8][4];
    #pragma unroll
    for (int i = 0; i < 4; i++)
        #pragma unroll
        for (int j = 0; j < 8; j++)
            #pragma unroll
            for (int q = 0; q < 4; q++) acc[i][j][q] = 0.f;

    auto issue = [&](int st, int kt) {
        float* As = smem + st * STAGE;
        float* Bs = As + ASZ;
        #pragma unroll
        for (int i = 0; i < 8; i++) {
            int li = tid + i * 256;
            int m = li >> 3, c = (li & 7) * 4;
            cp16(As + m * ASTR + c, Ap + (size_t)(bm + m) * lda + kt + c, true);
        }
        #pragma unroll
        for (int i = 0; i < 4; i++) {
            int li = tid + i * 256;
            int r = li >> 5, c4 = (li & 31) * 4;
            cp16(Bs + r * BSTR + c4, Bp + (size_t)(kt + r) * N + bn + c4, true);
        }
        asm volatile("cp.async.commit_group;\n" ::: "memory");
    };

    auto compute = [&](int st) {
        const unsigned* As = reinterpret_cast<const unsigned*>(smem + st * STAGE);
        const unsigned* Bs = As + ASZ;
        #pragma unroll
        for (int ks = 0; ks < BK / 8; ks++) {
            int kc = ks * 8 + (lane & 3);
            unsigned af[4][4];
            #pragma unroll
            for (int mi = 0; mi < 4; mi++) {
                int mr = wm * 64 + mi * 16 + (lane >> 2);
                af[mi][0] = As[mr * ASTR + kc];
                af[mi][1] = As[(mr + 8) * ASTR + kc];
                af[mi][2] = As[mr * ASTR + kc + 4];
                af[mi][3] = As[(mr + 8) * ASTR + kc + 4];
            }
            #pragma unroll
            for (int ni = 0; ni < 8; ni++) {
                int nc = wn * 64 + ni * 8 + (lane >> 2);
                unsigned b0 = Bs[kc * BSTR + nc];
                unsigned b1 = Bs[(kc + 4) * BSTR + nc];
                #pragma unroll
                for (int mi = 0; mi < 4; mi++) {
                    asm volatile(
                        "mma.sync.aligned.m16n8k8.row.col.f32.tf32.tf32.f32 "
                        "{%0,%1,%2,%3}, {%4,%5,%6,%7}, {%8,%9}, {%0,%1,%2,%3};\n"
                        : "+f"(acc[mi][ni][0]), "+f"(acc[mi][ni][1]),
                          "+f"(acc[mi][ni][2]), "+f"(acc[mi][ni][3])
                        : "r"(af[mi][0]), "r"(af[mi][1]), "r"(af[mi][2]), "r"(af[mi][3]),
                          "r"(b0), "r"(b1));
                }
            }
        }
    };

    int nt = Kd / BK;
    issue(0, 0);
    issue(1, BK);
    int st = 0;
    for (int i = 0; i < nt; i++) {
        if (i == nt - 1)
            asm volatile("cp.async.wait_group 0;\n" ::: "memory");
        else
            asm volatile("cp.async.wait_group 1;\n" ::: "memory");
        __syncthreads();
        if (i + 2 < nt) {
            int st2 = st + 2; if (st2 >= 3) st2 -= 3;
            issue(st2, (i + 2) * BK);
        }
        compute(st);
        if (++st == 3) st = 0;
    }

    // Epilogue
    #pragma unroll
    for (int mi = 0; mi < 4; mi++) {
        int r0 = bm + wm * 64 + mi * 16 + (lane >> 2);
        #pragma unroll
        for (int ni = 0; ni < 8; ni++) {
            int c0 = bn + wn * 64 + ni * 8 + (lane & 3) * 2;
            #pragma unroll
            for (int h = 0; h < 2; h++) {
                int rr = r0 + h * 8;
                float v0 = acc[mi][ni][h * 2 + 0];
                float v1 = acc[mi][ni][h * 2 + 1];
                if (EPI != 3) { v0 += bias[c0]; v1 += bias[c0 + 1]; }
                if (EPI == 1) {
                    v0 = (v0 > 20.0f) ? v0 : log1pf(__expf(v0));
                    v1 = (v1 > 20.0f) ? v1 : log1pf(__expf(v1));
                }
                *reinterpret_cast<float2*>(&Cp[(size_t)rr * N + c0]) = make_float2(v0, v1);
            }
        }
    }
}

// ---------------------------------------------------------------------------
// 128x64 3-stage pipelined GEMM (dbc split-K partials), no CVT in loop.
// ---------------------------------------------------------------------------
__global__ void __launch_bounds__(256) gemm_dbc(
    const float* __restrict__ A, const float* __restrict__ B,
    float* __restrict__ C, int N, int Kd, int lda, size_t partStride)
{
    constexpr int BM = 128, BK = 32, BN = 64;
    constexpr int ASTR = BK + 4, BSTR = BN + 8;
    constexpr int ASZ = BM * ASTR, BSZ = BK * BSTR, STAGE = ASZ + BSZ;

    extern __shared__ float smem[];

    int tid = threadIdx.x, lane = tid & 31, warp = tid >> 5;
    int wm = warp >> 1, wn = warp & 1;
    int bm = blockIdx.y * BM, bn = blockIdx.x * BN;
    int part = blockIdx.z;
    const float* Ap = A + (size_t)part * Kd;
    const float* Bp = B + (size_t)part * Kd * N;
    float* Cp = C + (size_t)part * partStride;

    float acc[2][4][4];
    #pragma unroll
    for (int i = 0; i < 2; i++)
        #pragma unroll
        for (int j = 0; j < 4; j++)
            #pragma unroll
            for (int q = 0; q < 4; q++) acc[i][j][q] = 0.f;

    auto issue = [&](int st, int kt) {
        float* As = smem + st * STAGE;
        float* Bs = As + ASZ;
        #pragma unroll
        for (int i = 0; i < 4; i++) {
            int li = tid + i * 256;
            int m = li >> 3, c = (li & 7) * 4;
            cp16(As + m * ASTR + c, Ap + (size_t)(bm + m) * lda + kt + c, true);
        }
        #pragma unroll
        for (int i = 0; i < 2; i++) {
            int li = tid + i * 256;
            int r = li >> 4, c4 = (li & 15) * 4;
            cp16(Bs + r * BSTR + c4, Bp + (size_t)(kt + r) * N + bn + c4,
                 (bn + c4) < N);
        }
        asm volatile("cp.async.commit_group;\n" ::: "memory");
    };

    auto compute = [&](int st) {
        const unsigned* As = reinterpret_cast<const unsigned*>(smem + st * STAGE);
        const unsigned* Bs = As + ASZ;
        #pragma unroll
        for (int ks = 0; ks < BK / 8; ks++) {
            int kc = ks * 8 + (lane & 3);
            unsigned af[2][4];
            #pragma unroll
            for (int mi = 0; mi < 2; mi++) {
                int mr = wm * 32 + mi * 16 + (lane >> 2);
                af[mi][0] = As[mr * ASTR + kc];
                af[mi][1] = As[(mr + 8) * ASTR + kc];
                af[mi][2] = As[mr * ASTR + kc + 4];
                af[mi][3] = As[(mr + 8) * ASTR + kc + 4];
            }
            #pragma unroll
            for (int ni = 0; ni < 4; ni++) {
                int nc = wn * 32 + ni * 8 + (lane >> 2);
                unsigned b0 = Bs[kc * BSTR + nc];
                unsigned b1 = Bs[(kc + 4) * BSTR + nc];
                #pragma unroll
                for (int mi = 0; mi < 2; mi++) {
                    asm volatile(
                        "mma.sync.aligned.m16n8k8.row.col.f32.tf32.tf32.f32 "
                        "{%0,%1,%2,%3}, {%4,%5,%6,%7}, {%8,%9}, {%0,%1,%2,%3};\n"
                        : "+f"(acc[mi][ni][0]), "+f"(acc[mi][ni][1]),
                          "+f"(acc[mi][ni][2]), "+f"(acc[mi][ni][3])
                        : "r"(af[mi][0]), "r"(af[mi][1]), "r"(af[mi][2]), "r"(af[mi][3]),
                          "r"(b0), "r"(b1));
                }
            }
        }
    };

    int nt = Kd / BK;
    issue(0, 0);
    issue(1, BK);
    int st = 0;
    for (int i = 0; i < nt; i++) {
        if (i == nt - 1)
            asm volatile("cp.async.wait_group 0;\n" ::: "memory");
        else
            asm volatile("cp.async.wait_group 1;\n" ::: "memory");
        __syncthreads();
        if (i + 2 < nt) {
            int st2 = st + 2; if (st2 >= 3) st2 -= 3;
            issue(st2, (i + 2) * BK);
        }
        compute(st);
        if (++st == 3) st = 0;
    }

    #pragma unroll
    for (int mi = 0; mi < 2; mi++) {
        int r0 = bm + wm * 32 + mi * 16 + (lane >> 2);
        #pragma unroll
        for (int ni = 0; ni < 4; ni++) {
            int c0 = bn + wn * 32 + ni * 8 + (lane & 3) * 2;
            if (c0 >= N) continue;
            #pragma unroll
            for (int h = 0; h < 2; h++) {
                int rr = r0 + h * 8;
                *reinterpret_cast<float2*>(&Cp[(size_t)rr * N + c0]) =
                    make_float2(acc[mi][ni][h * 2 + 0], acc[mi][ni][h * 2 + 1]);
            }
        }
    }
}

// ---------------------------------------------------------------------------
// Reduces
// ---------------------------------------------------------------------------
// dbc = sum of 8 partials + bias; delta cols (<128) rounded for dup GEMM.
__global__ void __launch_bounds__(256) reduce8_k(
    const float* __restrict__ P, const float* __restrict__ bias, float* __restrict__ C)
{
    const size_t PS = (size_t)NROWS * 160;
    size_t i = (size_t)blockIdx.x * 256 + threadIdx.x;
    int col = (int)(i % 160);
    float v = bias[col];
    #pragma unroll
    for (int p = 0; p < 8; p++) v += P[i + p * PS];
    C[i] = (col < 128) ? tf32r(v) : v;
}

// out = P0 + P1 + bias + residual
__global__ void __launch_bounds__(256) reduce2_out_k(
    const float* __restrict__ P, const float* __restrict__ bias,
    const float* __restrict__ x, float* __restrict__ C)
{
    const size_t PS = (size_t)NROWS * DMv;
    size_t i = ((size_t)blockIdx.x * 256 + threadIdx.x) * 4;
    float4 a = *reinterpret_cast<const float4*>(&P[i]);
    float4 b = *reinterpret_cast<const float4*>(&P[i + PS]);
    float4 r = *reinterpret_cast<const float4*>(&x[i]);
    const float4 bv = *reinterpret_cast<const float4*>(&bias[i % DMv]);
    float4 o;
    o.x = a.x + b.x + r.x + bv.x; o.y = a.y + b.y + r.y + bv.y;
    o.z = a.z + b.z + r.z + bv.z; o.w = a.w + b.w + r.w + bv.w;
    *reinterpret_cast<float4*>(&C[i]) = o;
}

// ---------------------------------------------------------------------------
// Depthwise causal conv (K=4) + SiLU -> x1c (plain) + x1cp (rounded)
// ---------------------------------------------------------------------------
__global__ void __launch_bounds__(256) conv_silu_k(
    const float* __restrict__ proj, const float* __restrict__ cw,
    const float* __restrict__ cb, float* __restrict__ out, float* __restrict__ outp)
{
    int d = blockIdx.x * 256 + threadIdx.x;
    int row = blockIdx.y;
    int t = row & (Tv - 1);
    int b = row >> 10;
    float4 w = *reinterpret_cast<const float4*>(cw + (size_t)d * 4);
    float acc = cb[d];
    const float* base = proj + (size_t)(b * Tv) * 4096 + d;
    if (t >= 3) acc = fmaf(base[(size_t)(t - 3) * 4096], w.x, acc);
    if (t >= 2) acc = fmaf(base[(size_t)(t - 2) * 4096], w.y, acc);
    if (t >= 1) acc = fmaf(base[(size_t)(t - 1) * 4096], w.z, acc);
    acc = fmaf(base[(size_t)t * 4096], w.w, acc);
    float sv = silu_f(acc);
    out[(size_t)row * Dv + d] = sv;
    outp[(size_t)row * Dv + d] = tf32r(sv);
}

// ---------------------------------------------------------------------------
// Selective scan, smem-staged (plain inputs). ymod written rounded.
// ---------------------------------------------------------------------------
__global__ void __launch_bounds__(256) scan_k(
    const float* __restrict__ dbc, const float* __restrict__ delta,
    const float* __restrict__ x1c, const float* __restrict__ proj,
    const float* __restrict__ A_log, float* __restrict__ ymod)
{
    __shared__ float Bs[128][16];
    __shared__ float Cs[128][16];
    __shared__ float De[128][16];
    __shared__ float Xs[128][16];
    __shared__ float Ys[128][16];
    int tid = threadIdx.x;
    int n = tid & 15, grp = tid >> 4;
    int b = blockIdx.y;
    int d0 = blockIdx.x * 16;
    float An = -__expf(A_log[(size_t)(d0 + grp) * NSTv + n]);
    float h = 0.f;

    for (int c = 0; c < 8; c++) {
        __syncthreads();
        int t0 = c * 128;
        for (int idx = tid; idx < 2048; idx += 256) {
            int tl = idx >> 4, nn = idx & 15;
            size_t r = (size_t)(b * Tv + t0 + tl) * 160;
            Bs[tl][nn] = dbc[r + 128 + nn];
            Cs[tl][nn] = dbc[r + 144 + nn];
            size_t rr = (size_t)(b * Tv + t0 + tl) * Dv + d0 + nn;
            De[tl][nn] = delta[rr];
            Xs[tl][nn] = x1c[rr];
        }
        __syncthreads();
        #pragma unroll 8
        for (int tl = 0; tl < 128; tl++) {
            float de = De[tl][grp];
            float xx = Xs[tl][grp];
            float a = __expf(de * An);
            h = fmaf(a, h, de * Bs[tl][n] * xx);
            float p = h * Cs[tl][n];
            p += __shfl_xor_sync(0xffffffffu, p, 8);
            p += __shfl_xor_sync(0xffffffffu, p, 4);
            p += __shfl_xor_sync(0xffffffffu, p, 2);
            p += __shfl_xor_sync(0xffffffffu, p, 1);
            if (n == 0) Ys[tl][grp] = p;
        }
        __syncthreads();
        for (int idx = tid; idx < 2048; idx += 256) {
            int tl = idx >> 4, dl2 = idx & 15;
            int row = b * Tv + t0 + tl;
            float g = proj[(size_t)row * 4096 + 2048 + d0 + dl2];
            ymod[(size_t)row * Dv + d0 + dl2] = tf32r(Ys[tl][dl2] * silu_f(g));
        }
    }
}

// ---------------------------------------------------------------------------
extern "C" void kernel_launch(void* const* d_in, const int* in_sizes, int n_in,
                              void* d_out, int out_size)
{
    const float* x      = (const float*)d_in[0];
    const float* rms_w  = (const float*)d_in[1];
    const float* in_W   = (const float*)d_in[2];
    const float* in_b   = (const float*)d_in[3];
    const float* conv_w = (const float*)d_in[4];
    const float* conv_b = (const float*)d_in[5];
    const float* A_log  = (const float*)d_in[6];
    const float* dbc_W  = (const float*)d_in[7];
    const float* dbc_b  = (const float*)d_in[8];
    const float* dup_W  = (const float*)d_in[9];
    const float* dup_b  = (const float*)d_in[10];
    const float* out_W  = (const float*)d_in[11];
    const float* out_b  = (const float*)d_in[12];
    float* out = (float*)d_out;

    float* S = nullptr;
    cudaGetSymbolAddress((void**)&S, g_scratch);

    const int SMBIG = 3 * (256 * 36 + 32 * 136) * 4;   // 162816 B
    const int SMDBC = 3 * (128 * 36 + 32 * 72) * 4;    //  82944 B
    cudaFuncSetAttribute(gemm_big<0>, cudaFuncAttributeMaxDynamicSharedMemorySize, SMBIG);
    cudaFuncSetAttribute(gemm_big<1>, cudaFuncAttributeMaxDynamicSharedMemorySize, SMBIG);
    cudaFuncSetAttribute(gemm_big<3>, cudaFuncAttributeMaxDynamicSharedMemorySize, SMBIG);
    cudaFuncSetAttribute(gemm_dbc,    cudaFuncAttributeMaxDynamicSharedMemorySize, SMDBC);

    // 0. Round weights (tf32 RNA, same layout)
    round_k<<<(1024 * 4096) / 1024, 256>>>(in_W,  S + OFF_WINR);
    round_k<<<(2048 * 160)  / 1024, 256>>>(dbc_W, S + OFF_WDBCR);
    round_k<<<(128 * 2048)  / 1024, 256>>>(dup_W, S + OFF_WDUPR);
    round_k<<<(2048 * 1024) / 1024, 256>>>(out_W, S + OFF_WOUTR);

    // 1. RMSNorm -> h (rounded)
    rmsnorm_k<<<NROWS, 256>>>(x, rms_w, S + OFF_H);

    // 2. in_proj: (2048x1024)@(1024x4096)
    gemm_big<0><<<dim3(32, 8, 1), 256, SMBIG>>>(
        S + OFF_H, S + OFF_WINR, in_b, S + OFF_PROJ, 4096, 1024, 1024, 0);

    // 3. depthwise conv + SiLU -> x1c (plain) + x1cp (rounded)
    conv_silu_k<<<dim3(Dv / 256, NROWS), 256>>>(
        S + OFF_PROJ, conv_w, conv_b, S + OFF_X1C, S + OFF_X1CP);

    // 4. dbc: (2048x2048)@(2048x160), split-K x8 + reduce
    gemm_dbc<<<dim3(3, 16, 8), 256, SMDBC>>>(
        S + OFF_X1CP, S + OFF_WDBCR, S + OFF_DBCP, 160, 256, 2048,
        (size_t)NROWS * 160);
    reduce8_k<<<(NROWS * 160) / 256, 256>>>(S + OFF_DBCP, dbc_b, S + OFF_DBC);

    // 5. delta up-proj + softplus: (2048x128)@(128x2048)
    gemm_big<1><<<dim3(16, 8, 1), 256, SMBIG>>>(
        S + OFF_DBC, S + OFF_WDUPR, dup_b, S + OFF_DELTA, 2048, 128, 160, 0);

    // 6. selective scan + silu(g) gating -> ymod (rounded)
    scan_k<<<dim3(Dv / 16, 2), 256>>>(
        S + OFF_DBC, S + OFF_DELTA, S + OFF_X1C, S + OFF_PROJ, A_log, S + OFF_YMOD);

    // 7. out_proj split-K x2 + fused reduce
    gemm_big<3><<<dim3(8, 8, 2), 256, SMBIG>>>(
        S + OFF_YMOD, S + OFF_WOUTR, nullptr, S + OFF_OUTP, 1024, 1024, 2048,
        (size_t)NROWS * DMv);
    reduce2_out_k<<<(NROWS * DMv) / 1024, 256>>>(S + OFF_OUTP, out_b, x, out);
}

// round 14
// speedup vs baseline: 1.2590x; 1.2590x over previous
#include <cuda_runtime.h>
#include <cuda_fp16.h>
#include <cstdint>

// ---------------------------------------------------------------------------
// MambaBlock: B=2, T=1024, DM=1024, D=2048, N=16, K=4, DTR=128
// Round 14: fp16 tensor-core GEMMs (mma.m16n8k16, ldmatrix fragments, 3-stage
// cp.async). fp16 keeps tf32's 10-bit mantissa; operands are O(1) -> in range.
// Scan / conv / reductions remain fp32.
// ---------------------------------------------------------------------------

#define DMv   1024
#define Dv    2048
#define Tv    1024
#define NROWS 2048
#define NSTv  16

// Scratch layout (float units; half buffers use half the element count)
#define OFF_H      0u          // h half [2048*1024]
#define OFF_PROJ   1048576u    // float [2048*4096]
#define OFF_X1C    9437184u    // float [2048*2048] (scan)
#define OFF_X1CP   13631488u   // half  [2048*2048] (dbc A)
#define OFF_DBC    15728640u   // float [2048*160]  (B/C cols 128..159 used)
#define OFF_DELTAH 16056320u   // half  [2048*128]  (dup A, raw delta)
#define OFF_DELTA  16187392u   // float [2048*2048] (softplus out, scan)
#define OFF_YMOD   20381696u   // half  [2048*2048]
#define OFF_DBCP   22478848u   // float [8*2048*160]
#define OFF_OUTP   25100288u   // float [2*2048*1024]
#define OFF_WINR   29294592u   // half  in_W
#define OFF_WDBCR  31391744u   // half  dbc_W
#define OFF_WDUPR  31555584u   // half  dup_W
#define OFF_WOUTR  31686656u   // half  out_W
#define SCRATCH_FLOATS 32735232u

__device__ __align__(128) float g_scratch[SCRATCH_FLOATS];

__device__ __forceinline__ float silu_f(float v) {
    return v * (1.0f / (1.0f + __expf(-v)));
}
__device__ __forceinline__ void cp16g(void* dst, const void* src, bool p) {
    unsigned d = (unsigned)__cvta_generic_to_shared(dst);
    int sz = p ? 16 : 0;
    asm volatile("cp.async.cg.shared.global [%0], [%1], 16, %2;\n"
                 :: "r"(d), "l"(src), "r"(sz));
}
__device__ __forceinline__ void ldsm_x4(unsigned& r0, unsigned& r1,
                                        unsigned& r2, unsigned& r3, unsigned a) {
    asm volatile("ldmatrix.sync.aligned.m8n8.x4.shared.b16 {%0,%1,%2,%3}, [%4];"
                 : "=r"(r0), "=r"(r1), "=r"(r2), "=r"(r3) : "r"(a));
}
__device__ __forceinline__ void ldsm_x4t(unsigned& r0, unsigned& r1,
                                         unsigned& r2, unsigned& r3, unsigned a) {
    asm volatile("ldmatrix.sync.aligned.m8n8.x4.trans.shared.b16 {%0,%1,%2,%3}, [%4];"
                 : "=r"(r0), "=r"(r1), "=r"(r2), "=r"(r3) : "r"(a));
}
#define MMA16816(acc, a, b0, b1) \
    asm volatile( \
        "mma.sync.aligned.m16n8k16.row.col.f32.f16.f16.f32 " \
        "{%0,%1,%2,%3}, {%4,%5,%6,%7}, {%8,%9}, {%0,%1,%2,%3};\n" \
        : "+f"((acc)[0]), "+f"((acc)[1]), "+f"((acc)[2]), "+f"((acc)[3]) \
        : "r"((a)[0]), "r"((a)[1]), "r"((a)[2]), "r"((a)[3]), "r"(b0), "r"(b1))

// ---------------------------------------------------------------------------
// Weight convert: float -> half, same layout. size % 1024 == 0.
// ---------------------------------------------------------------------------
__global__ void __launch_bounds__(256) roundh_k(
    const float* __restrict__ W, __half* __restrict__ Wh)
{
    size_t i = ((size_t)blockIdx.x * 256 + threadIdx.x) * 4;
    float4 v = *reinterpret_cast<const float4*>(&W[i]);
    __half2 p0 = __floats2half2_rn(v.x, v.y);
    __half2 p1 = __floats2half2_rn(v.z, v.w);
    uint2 u = make_uint2(*reinterpret_cast<unsigned*>(&p0),
                         *reinterpret_cast<unsigned*>(&p1));
    *reinterpret_cast<uint2*>(Wh + i) = u;
}

// ---------------------------------------------------------------------------
// RMSNorm -> h (half)
// ---------------------------------------------------------------------------
__global__ void __launch_bounds__(256) rmsnorm_k(
    const float* __restrict__ x, const float* __restrict__ w, __half* __restrict__ out)
{
    int row = blockIdx.x;
    const float4* xr = reinterpret_cast<const float4*>(x + (size_t)row * DMv);
    float4 v = xr[threadIdx.x];
    float s = v.x * v.x + v.y * v.y + v.z * v.z + v.w * v.w;
    #pragma unroll
    for (int o = 16; o; o >>= 1) s += __shfl_xor_sync(0xffffffffu, s, o);
    __shared__ float ws[8];
    if ((threadIdx.x & 31) == 0) ws[threadIdx.x >> 5] = s;
    __syncthreads();
    float tot = 0.f;
    #pragma unroll
    for (int i = 0; i < 8; i++) tot += ws[i];
    float scale = rsqrtf(tot * (1.0f / (float)DMv) + 1e-6f);
    float4 wv = reinterpret_cast<const float4*>(w)[threadIdx.x];
    __half2 p0 = __floats2half2_rn(v.x * scale * wv.x, v.y * scale * wv.y);
    __half2 p1 = __floats2half2_rn(v.z * scale * wv.z, v.w * scale * wv.w);
    uint2 u = make_uint2(*reinterpret_cast<unsigned*>(&p0),
                         *reinterpret_cast<unsigned*>(&p1));
    *reinterpret_cast<uint2*>(out + (size_t)row * DMv + threadIdx.x * 4) = u;
}

// ---------------------------------------------------------------------------
// fp16 big-tile GEMM: BM=256, BN=128, BK=32 (2 k16 steps / tile), 3-stage.
// 8 warps as 4(M)x2(N), warp tile 64x64. EPI 0:+bias 1:+bias,softplus 3:raw.
// ---------------------------------------------------------------------------
template <int EPI>
__global__ void __launch_bounds__(256) gemm_big(
    const __half* __restrict__ A, const __half* __restrict__ B,
    const float* __restrict__ bias, float* __restrict__ C,
    int N, int Kd, int lda, size_t partStride)
{
    constexpr int BM = 256, BN = 128, BK = 32;
    constexpr int ASTR = BK + 8;            // 40 halfs (80 B, 16B-aligned rows)
    constexpr int BSTR = BN + 8;            // 136 halfs
    constexpr int ASZ = BM * ASTR, BSZ = BK * BSTR, STAGE = ASZ + BSZ;

    extern __shared__ __half smem[];
    unsigned sbase = (unsigned)__cvta_generic_to_shared(smem);

    int tid = threadIdx.x, lane = tid & 31, warp = tid >> 5;
    int wm = warp >> 1, wn = warp & 1;
    int bm = blockIdx.y * BM, bn = blockIdx.x * BN;
    int part = blockIdx.z;
    const __half* Ap = A + (size_t)part * Kd;
    const __half* Bp = B + (size_t)part * Kd * N;
    float* Cp = C + (size_t)part * partStride;

    float acc[4][8][4];
    #pragma unroll
    for (int i = 0; i < 4; i++)
        #pragma unroll
        for (int j = 0; j < 8; j++)
            #pragma unroll
            for (int q = 0; q < 4; q++) acc[i][j][q] = 0.f;

    auto issue = [&](int st, int kt) {
        __half* As = smem + st * STAGE;
        __half* Bs = As + ASZ;
        #pragma unroll
        for (int i = 0; i < 4; i++) {      // A: 256 rows x 64B = 1024 chunks
            int li = tid + i * 256;
            int m = li >> 2, c = (li & 3) * 8;
            cp16g(As + m * ASTR + c, Ap + (size_t)(bm + m) * lda + kt + c, true);
        }
        #pragma unroll
        for (int i = 0; i < 2; i++) {      // B: 32 rows x 256B = 512 chunks
            int li = tid + i * 256;
            int r = li >> 4, c8 = (li & 15) * 8;
            cp16g(Bs + r * BSTR + c8, Bp + (size_t)(kt + r) * N + bn + c8, true);
        }
        asm volatile("cp.async.commit_group;\n" ::: "memory");
    };

    int g = lane >> 3, lr = lane & 7;
    auto compute = [&](int st) {
        unsigned abase = sbase + (st * STAGE) * 2;
        unsigned bbase = abase + ASZ * 2;
        #pragma unroll
        for (int ks = 0; ks < 2; ks++) {
            int k0 = ks * 16;
            unsigned af[4][4];
            #pragma unroll
            for (int mi = 0; mi < 4; mi++) {
                int row = wm * 64 + mi * 16 + (g & 1) * 8 + lr;
                int col = k0 + (g >> 1) * 8;
                ldsm_x4(af[mi][0], af[mi][1], af[mi][2], af[mi][3],
                        abase + (row * ASTR + col) * 2);
            }
            #pragma unroll
            for (int p = 0; p < 4; p++) {
                int row = k0 + (g & 1) * 8 + lr;
                int col = wn * 64 + p * 16 + (g >> 1) * 8;
                unsigned b0, b1, b2, b3;
                ldsm_x4t(b0, b1, b2, b3, bbase + (row * BSTR + col) * 2);
                #pragma unroll
                for (int mi = 0; mi < 4; mi++) {
                    MMA16816(acc[mi][2 * p], af[mi], b0, b1);
                    MMA16816(acc[mi][2 * p + 1], af[mi], b2, b3);
                }
            }
        }
    };

    int nt = Kd / BK;
    issue(0, 0);
    issue(1, BK);
    int st = 0;
    for (int i = 0; i < nt; i++) {
        if (i == nt - 1)
            asm volatile("cp.async.wait_group 0;\n" ::: "memory");
        else
            asm volatile("cp.async.wait_group 1;\n" ::: "memory");
        __syncthreads();
        if (i + 2 < nt) {
            int st2 = st + 2; if (st2 >= 3) st2 -= 3;
            issue(st2, (i + 2) * BK);
        }
        compute(st);
        if (++st == 3) st = 0;
    }

    // Epilogue
    #pragma unroll
    for (int mi = 0; mi < 4; mi++) {
        int r0 = bm + wm * 64 + mi * 16 + (lane >> 2);
        #pragma unroll
        for (int ni = 0; ni < 8; ni++) {
            int c0 = bn + wn * 64 + ni * 8 + (lane & 3) * 2;
            #pragma unroll
            for (int h = 0; h < 2; h++) {
                int rr = r0 + h * 8;
                float v0 = acc[mi][ni][h * 2 + 0];
                float v1 = acc[mi][ni][h * 2 + 1];
                if (EPI != 3) { v0 += bias[c0]; v1 += bias[c0 + 1]; }
                if (EPI == 1) {
                    v0 = (v0 > 20.0f) ? v0 : log1pf(__expf(v0));
                    v1 = (v1 > 20.0f) ? v1 : log1pf(__expf(v1));
                }
                *reinterpret_cast<float2*>(&Cp[(size_t)rr * N + c0]) = make_float2(v0, v1);
            }
        }
    }
}

// ---------------------------------------------------------------------------
// fp16 128x64 GEMM (dbc split-K partials). Warp tile 32x32.
// ---------------------------------------------------------------------------
__global__ void __launch_bounds__(256) gemm_dbc(
    const __half* __restrict__ A, const __half* __restrict__ B,
    float* __restrict__ C, int N, int Kd, int lda, size_t partStride)
{
    constexpr int BM = 128, BN = 64, BK = 32;
    constexpr int ASTR = BK + 8, BSTR = BN + 8;   // 40 / 72 halfs
    constexpr int ASZ = BM * ASTR, BSZ = BK * BSTR, STAGE = ASZ + BSZ;

    extern __shared__ __half smem[];
    unsigned sbase = (unsigned)__cvta_generic_to_shared(smem);

    int tid = threadIdx.x, lane = tid & 31, warp = tid >> 5;
    int wm = warp >> 1, wn = warp & 1;
    int bm = blockIdx.y * BM, bn = blockIdx.x * BN;
    int part = blockIdx.z;
    const __half* Ap = A + (size_t)part * Kd;
    const __half* Bp = B + (size_t)part * Kd * N;
    float* Cp = C + (size_t)part * partStride;

    float acc[2][4][4];
    #pragma unroll
    for (int i = 0; i < 2; i++)
        #pragma unroll
        for (int j = 0; j < 4; j++)
            #pragma unroll
            for (int q = 0; q < 4; q++) acc[i][j][q] = 0.f;

    auto issue = [&](int st, int kt) {
        __half* As = smem + st * STAGE;
        __half* Bs = As + ASZ;
        #pragma unroll
        for (int i = 0; i < 2; i++) {      // A: 128 x 64B = 512 chunks
            int li = tid + i * 256;
            int m = li >> 2, c = (li & 3) * 8;
            cp16g(As + m * ASTR + c, Ap + (size_t)(bm + m) * lda + kt + c, true);
        }
        {                                   // B: 32 x 128B = 256 chunks
            int li = tid;
            if (li < 256) {
                int r = li >> 3, c8 = (li & 7) * 8;
                cp16g(Bs + r * BSTR + c8, Bp + (size_t)(kt + r) * N + bn + c8,
                      (bn + c8) < N);
            }
        }
        asm volatile("cp.async.commit_group;\n" ::: "memory");
    };

    int g = lane >> 3, lr = lane & 7;
    auto compute = [&](int st) {
        unsigned abase = sbase + (st * STAGE) * 2;
        unsigned bbase = abase + ASZ * 2;
        #pragma unroll
        for (int ks = 0; ks < 2; ks++) {
            int k0 = ks * 16;
            unsigned af[2][4];
            #pragma unroll
            for (int mi = 0; mi < 2; mi++) {
                int row = wm * 32 + mi * 16 + (g & 1) * 8 + lr;
                int col = k0 + (g >> 1) * 8;
                ldsm_x4(af[mi][0], af[mi][1], af[mi][2], af[mi][3],
                        abase + (row * ASTR + col) * 2);
            }
            #pragma unroll
            for (int p = 0; p < 2; p++) {
                int row = k0 + (g & 1) * 8 + lr;
                int col = wn * 32 + p * 16 + (g >> 1) * 8;
                unsigned b0, b1, b2, b3;
                ldsm_x4t(b0, b1, b2, b3, bbase + (row * BSTR + col) * 2);
                #pragma unroll
                for (int mi = 0; mi < 2; mi++) {
                    MMA16816(acc[mi][2 * p], af[mi], b0, b1);
                    MMA16816(acc[mi][2 * p + 1], af[mi], b2, b3);
                }
            }
        }
    };

    int nt = Kd / BK;
    issue(0, 0);
    issue(1, BK);
    int st = 0;
    for (int i = 0; i < nt; i++) {
        if (i == nt - 1)
            asm volatile("cp.async.wait_group 0;\n" ::: "memory");
        else
            asm volatile("cp.async.wait_group 1;\n" ::: "memory");
        __syncthreads();
        if (i + 2 < nt) {
            int st2 = st + 2; if (st2 >= 3) st2 -= 3;
            issue(st2, (i + 2) * BK);
        }
        compute(st);
        if (++st == 3) st = 0;
    }

    #pragma unroll
    for (int mi = 0; mi < 2; mi++) {
        int r0 = bm + wm * 32 + mi * 16 + (lane >> 2);
        #pragma unroll
        for (int ni = 0; ni < 4; ni++) {
            int c0 = bn + wn * 32 + ni * 8 + (lane & 3) * 2;
            if (c0 >= N) continue;
            #pragma unroll
            for (int h = 0; h < 2; h++) {
                int rr = r0 + h * 8;
                *reinterpret_cast<float2*>(&Cp[(size_t)rr * N + c0]) =
                    make_float2(acc[mi][ni][h * 2 + 0], acc[mi][ni][h * 2 + 1]);
            }
        }
    }
}

// ---------------------------------------------------------------------------
// Reduces
// ---------------------------------------------------------------------------
// dbc: sum 8 partials + bias. Cols <128 -> deltah (half, raw delta, dup A);
// cols 128..159 -> dbc float (scan B/C).
__global__ void __launch_bounds__(256) reduce8_k(
    const float* __restrict__ P, const float* __restrict__ bias,
    float* __restrict__ C, __half* __restrict__ Dh)
{
    const size_t PS = (size_t)NROWS * 160;
    size_t i = (size_t)blockIdx.x * 256 + threadIdx.x;
    int col = (int)(i % 160);
    size_t row = i / 160;
    float v = bias[col];
    #pragma unroll
    for (int p = 0; p < 8; p++) v += P[i + p * PS];
    if (col < 128) Dh[row * 128 + col] = __float2half(v);
    else           C[i] = v;
}

// out = P0 + P1 + bias + residual
__global__ void __launch_bounds__(256) reduce2_out_k(
    const float* __restrict__ P, const float* __restrict__ bias,
    const float* __restrict__ x, float* __restrict__ C)
{
    const size_t PS = (size_t)NROWS * DMv;
    size_t i = ((size_t)blockIdx.x * 256 + threadIdx.x) * 4;
    float4 a = *reinterpret_cast<const float4*>(&P[i]);
    float4 b = *reinterpret_cast<const float4*>(&P[i + PS]);
    float4 r = *reinterpret_cast<const float4*>(&x[i]);
    const float4 bv = *reinterpret_cast<const float4*>(&bias[i % DMv]);
    float4 o;
    o.x = a.x + b.x + r.x + bv.x; o.y = a.y + b.y + r.y + bv.y;
    o.z = a.z + b.z + r.z + bv.z; o.w = a.w + b.w + r.w + bv.w;
    *reinterpret_cast<float4*>(&C[i]) = o;
}

// ---------------------------------------------------------------------------
// Depthwise causal conv (K=4) + SiLU -> x1c (float, scan) + x1cp (half, GEMM)
// ---------------------------------------------------------------------------
__global__ void __launch_bounds__(256) conv_silu_k(
    const float* __restrict__ proj, const float* __restrict__ cw,
    const float* __restrict__ cb, float* __restrict__ out, __half* __restrict__ outp)
{
    int d = blockIdx.x * 256 + threadIdx.x;
    int row = blockIdx.y;
    int t = row & (Tv - 1);
    int b = row >> 10;
    float4 w = *reinterpret_cast<const float4*>(cw + (size_t)d * 4);
    float acc = cb[d];
    const float* base = proj + (size_t)(b * Tv) * 4096 + d;
    if (t >= 3) acc = fmaf(base[(size_t)(t - 3) * 4096], w.x, acc);
    if (t >= 2) acc = fmaf(base[(size_t)(t - 2) * 4096], w.y, acc);
    if (t >= 1) acc = fmaf(base[(size_t)(t - 1) * 4096], w.z, acc);
    acc = fmaf(base[(size_t)t * 4096], w.w, acc);
    float sv = silu_f(acc);
    out[(size_t)row * Dv + d] = sv;
    outp[(size_t)row * Dv + d] = __float2half(sv);
}

// ---------------------------------------------------------------------------
// Selective scan, smem-staged (float inputs). ymod written half.
// ---------------------------------------------------------------------------
__global__ void __launch_bounds__(256) scan_k(
    const float* __restrict__ dbc, const float* __restrict__ delta,
    const float* __restrict__ x1c, const float* __restrict__ proj,
    const float* __restrict__ A_log, __half* __restrict__ ymod)
{
    __shared__ float Bs[128][16];
    __shared__ float Cs[128][16];
    __shared__ float De[128][16];
    __shared__ float Xs[128][16];
    __shared__ float Ys[128][16];
    int tid = threadIdx.x;
    int n = tid & 15, grp = tid >> 4;
    int b = blockIdx.y;
    int d0 = blockIdx.x * 16;
    float An = -__expf(A_log[(size_t)(d0 + grp) * NSTv + n]);
    float h = 0.f;

    for (int c = 0; c < 8; c++) {
        __syncthreads();
        int t0 = c * 128;
        for (int idx = tid; idx < 2048; idx += 256) {
            int tl = idx >> 4, nn = idx & 15;
            size_t r = (size_t)(b * Tv + t0 + tl) * 160;
            Bs[tl][nn] = dbc[r + 128 + nn];
            Cs[tl][nn] = dbc[r + 144 + nn];
            size_t rr = (size_t)(b * Tv + t0 + tl) * Dv + d0 + nn;
            De[tl][nn] = delta[rr];
            Xs[tl][nn] = x1c[rr];
        }
        __syncthreads();
        #pragma unroll 8
        for (int tl = 0; tl < 128; tl++) {
            float de = De[tl][grp];
            float xx = Xs[tl][grp];
            float a = __expf(de * An);
            h = fmaf(a, h, de * Bs[tl][n] * xx);
            float p = h * Cs[tl][n];
            p += __shfl_xor_sync(0xffffffffu, p, 8);
            p += __shfl_xor_sync(0xffffffffu, p, 4);
            p += __shfl_xor_sync(0xffffffffu, p, 2);
            p += __shfl_xor_sync(0xffffffffu, p, 1);
            if (n == 0) Ys[tl][grp] = p;
        }
        __syncthreads();
        for (int idx = tid; idx < 2048; idx += 256) {
            int tl = idx >> 4, dl2 = idx & 15;
            int row = b * Tv + t0 + tl;
            float g = proj[(size_t)row * 4096 + 2048 + d0 + dl2];
            ymod[(size_t)row * Dv + d0 + dl2] = __float2half(Ys[tl][dl2] * silu_f(g));
        }
    }
}

// ---------------------------------------------------------------------------
extern "C" void kernel_launch(void* const* d_in, const int* in_sizes, int n_in,
                              void* d_out, int out_size)
{
    const float* x      = (const float*)d_in[0];
    const float* rms_w  = (const float*)d_in[1];
    const float* in_W   = (const float*)d_in[2];
    const float* in_b   = (const float*)d_in[3];
    const float* conv_w = (const float*)d_in[4];
    const float* conv_b = (const float*)d_in[5];
    const float* A_log  = (const float*)d_in[6];
    const float* dbc_W  = (const float*)d_in[7];
    const float* dbc_b  = (const float*)d_in[8];
    const float* dup_W  = (const float*)d_in[9];
    const float* dup_b  = (const float*)d_in[10];
    const float* out_W  = (const float*)d_in[11];
    const float* out_b  = (const float*)d_in[12];
    float* out = (float*)d_out;

    float* S = nullptr;
    cudaGetSymbolAddress((void**)&S, g_scratch);
    __half* Hh    = (__half*)(S + OFF_H);
    __half* X1cp  = (__half*)(S + OFF_X1CP);
    __half* Dh    = (__half*)(S + OFF_DELTAH);
    __half* Ymodh = (__half*)(S + OFF_YMOD);
    __half* Win   = (__half*)(S + OFF_WINR);
    __half* Wdbc  = (__half*)(S + OFF_WDBCR);
    __half* Wdup  = (__half*)(S + OFF_WDUPR);
    __half* Wout  = (__half*)(S + OFF_WOUTR);

    const int SMBIG = 3 * (256 * 40 + 32 * 136) * 2;   // 87552 B
    const int SMDBC = 3 * (128 * 40 + 32 * 72) * 2;    // 44544 B
    cudaFuncSetAttribute(gemm_big<0>, cudaFuncAttributeMaxDynamicSharedMemorySize, SMBIG);
    cudaFuncSetAttribute(gemm_big<1>, cudaFuncAttributeMaxDynamicSharedMemorySize, SMBIG);
    cudaFuncSetAttribute(gemm_big<3>, cudaFuncAttributeMaxDynamicSharedMemorySize, SMBIG);
    cudaFuncSetAttribute(gemm_dbc,    cudaFuncAttributeMaxDynamicSharedMemorySize, SMDBC);

    // 0. Convert weights to half
    roundh_k<<<(1024 * 4096) / 1024, 256>>>(in_W,  Win);
    roundh_k<<<(2048 * 160)  / 1024, 256>>>(dbc_W, Wdbc);
    roundh_k<<<(128 * 2048)  / 1024, 256>>>(dup_W, Wdup);
    roundh_k<<<(2048 * 1024) / 1024, 256>>>(out_W, Wout);

    // 1. RMSNorm -> h (half)
    rmsnorm_k<<<NROWS, 256>>>(x, rms_w, Hh);

    // 2. in_proj: (2048x1024)@(1024x4096)
    gemm_big<0><<<dim3(32, 8, 1), 256, SMBIG>>>(
        Hh, Win, in_b, S + OFF_PROJ, 4096, 1024, 1024, 0);

    // 3. depthwise conv + SiLU
    conv_silu_k<<<dim3(Dv / 256, NROWS), 256>>>(
        S + OFF_PROJ, conv_w, conv_b, S + OFF_X1C, X1cp);

    // 4. dbc: (2048x2048)@(2048x160), split-K x8 + reduce
    gemm_dbc<<<dim3(3, 16, 8), 256, SMDBC>>>(
        X1cp, Wdbc, S + OFF_DBCP, 160, 256, 2048, (size_t)NROWS * 160);
    reduce8_k<<<(NROWS * 160) / 256, 256>>>(S + OFF_DBCP, dbc_b, S + OFF_DBC, Dh);

    // 5. delta up-proj + softplus: (2048x128)@(128x2048)
    gemm_big<1><<<dim3(16, 8, 1), 256, SMBIG>>>(
        Dh, Wdup, dup_b, S + OFF_DELTA, 2048, 128, 128, 0);

    // 6. selective scan + silu(g) gating -> ymod (half)
    scan_k<<<dim3(Dv / 16, 2), 256>>>(
        S + OFF_DBC, S + OFF_DELTA, S + OFF_X1C, S + OFF_PROJ, A_log, Ymodh);

    // 7. out_proj split-K x2 + fused reduce
    gemm_big<3><<<dim3(8, 8, 2), 256, SMBIG>>>(
        Ymodh, Wout, nullptr, S + OFF_OUTP, 1024, 1024, 2048,
        (size_t)NROWS * DMv);
    reduce2_out_k<<<(NROWS * DMv) / 1024, 256>>>(S + OFF_OUTP, out_b, x, out);
}

// round 16
// speedup vs baseline: 1.2838x; 1.0197x over previous
#include <cuda_runtime.h>
#include <cuda_fp16.h>
#include <cstdint>

// ---------------------------------------------------------------------------
// MambaBlock: B=2, T=1024, DM=1024, D=2048, N=16, K=4, DTR=128
// Round 16 (= round 15 with the gemm_med capture-order compile fix):
// fp16 mma GEMMs (m16n8k16 + ldmatrix + 3-stage cp.async); merged weight
// convert; dup GEMM on 128x128 tiles (grid 256); out_proj split-K x4.
// ---------------------------------------------------------------------------

#define DMv   1024
#define Dv    2048
#define Tv    1024
#define NROWS 2048
#define NSTv  16

// Scratch layout (float units)
#define OFF_H      0u          // half [2048*1024]
#define OFF_PROJ   1048576u    // float [2048*4096]
#define OFF_X1C    9437184u    // float [2048*2048] (scan)
#define OFF_X1CP   13631488u   // half  [2048*2048] (dbc A)
#define OFF_DBC    15728640u   // float [2048*160]  (B/C cols)
#define OFF_DELTAH 16056320u   // half  [2048*128]  (dup A)
#define OFF_DELTA  16187392u   // float [2048*2048] (scan)
#define OFF_YMOD   20381696u   // half  [2048*2048]
#define OFF_DBCP   22478848u   // float [8*2048*160]
#define OFF_OUTP   25100288u   // float [4*2048*1024]
#define OFF_WINR   33488896u   // half in_W
#define OFF_WDBCR  35586048u   // half dbc_W
#define OFF_WDUPR  35749888u   // half dup_W
#define OFF_WOUTR  35880960u   // half out_W
#define SCRATCH_FLOATS 36929536u

__device__ __align__(128) float g_scratch[SCRATCH_FLOATS];

__device__ __forceinline__ float silu_f(float v) {
    return v * (1.0f / (1.0f + __expf(-v)));
}
__device__ __forceinline__ void cp16g(void* dst, const void* src, bool p) {
    unsigned d = (unsigned)__cvta_generic_to_shared(dst);
    int sz = p ? 16 : 0;
    asm volatile("cp.async.cg.shared.global [%0], [%1], 16, %2;\n"
                 :: "r"(d), "l"(src), "r"(sz));
}
__device__ __forceinline__ void ldsm_x4(unsigned& r0, unsigned& r1,
                                        unsigned& r2, unsigned& r3, unsigned a) {
    asm volatile("ldmatrix.sync.aligned.m8n8.x4.shared.b16 {%0,%1,%2,%3}, [%4];"
                 : "=r"(r0), "=r"(r1), "=r"(r2), "=r"(r3) : "r"(a));
}
__device__ __forceinline__ void ldsm_x4t(unsigned& r0, unsigned& r1,
                                         unsigned& r2, unsigned& r3, unsigned a) {
    asm volatile("ldmatrix.sync.aligned.m8n8.x4.trans.shared.b16 {%0,%1,%2,%3}, [%4];"
                 : "=r"(r0), "=r"(r1), "=r"(r2), "=r"(r3) : "r"(a));
}
#define MMA16816(acc, a, b0, b1) \
    asm volatile( \
        "mma.sync.aligned.m16n8k16.row.col.f32.f16.f16.f32 " \
        "{%0,%1,%2,%3}, {%4,%5,%6,%7}, {%8,%9}, {%0,%1,%2,%3};\n" \
        : "+f"((acc)[0]), "+f"((acc)[1]), "+f"((acc)[2]), "+f"((acc)[3]) \
        : "r"((a)[0]), "r"((a)[1]), "r"((a)[2]), "r"((a)[3]), "r"(b0), "r"(b1))

// ---------------------------------------------------------------------------
// Merged weight convert: all 4 weight matrices float->half in one launch.
// ---------------------------------------------------------------------------
#define WSZ1 4194304u   // in_W
#define WSZ2 327680u    // dbc_W
#define WSZ3 262144u    // dup_W
#define WSZ4 2097152u   // out_W
__global__ void __launch_bounds__(256) convw_k(
    const float* __restrict__ inW, const float* __restrict__ dbcW,
    const float* __restrict__ dupW, const float* __restrict__ outW,
    __half* __restrict__ oin, __half* __restrict__ odbc,
    __half* __restrict__ odup, __half* __restrict__ oout)
{
    size_t i = ((size_t)blockIdx.x * 256 + threadIdx.x) * 4;
    const float* src; __half* dst; size_t off;
    if (i < WSZ1)                     { src = inW;  dst = oin;  off = i; }
    else if (i < WSZ1 + WSZ2)         { src = dbcW; dst = odbc; off = i - WSZ1; }
    else if (i < WSZ1 + WSZ2 + WSZ3)  { src = dupW; dst = odup; off = i - WSZ1 - WSZ2; }
    else                              { src = outW; dst = oout; off = i - WSZ1 - WSZ2 - WSZ3; }
    float4 v = *reinterpret_cast<const float4*>(&src[off]);
    __half2 p0 = __floats2half2_rn(v.x, v.y);
    __half2 p1 = __floats2half2_rn(v.z, v.w);
    uint2 u = make_uint2(*reinterpret_cast<unsigned*>(&p0),
                         *reinterpret_cast<unsigned*>(&p1));
    *reinterpret_cast<uint2*>(dst + off) = u;
}

// ---------------------------------------------------------------------------
// RMSNorm -> h (half)
// ---------------------------------------------------------------------------
__global__ void __launch_bounds__(256) rmsnorm_k(
    const float* __restrict__ x, const float* __restrict__ w, __half* __restrict__ out)
{
    int row = blockIdx.x;
    const float4* xr = reinterpret_cast<const float4*>(x + (size_t)row * DMv);
    float4 v = xr[threadIdx.x];
    float s = v.x * v.x + v.y * v.y + v.z * v.z + v.w * v.w;
    #pragma unroll
    for (int o = 16; o; o >>= 1) s += __shfl_xor_sync(0xffffffffu, s, o);
    __shared__ float ws[8];
    if ((threadIdx.x & 31) == 0) ws[threadIdx.x >> 5] = s;
    __syncthreads();
    float tot = 0.f;
    #pragma unroll
    for (int i = 0; i < 8; i++) tot += ws[i];
    float scale = rsqrtf(tot * (1.0f / (float)DMv) + 1e-6f);
    float4 wv = reinterpret_cast<const float4*>(w)[threadIdx.x];
    __half2 p0 = __floats2half2_rn(v.x * scale * wv.x, v.y * scale * wv.y);
    __half2 p1 = __floats2half2_rn(v.z * scale * wv.z, v.w * scale * wv.w);
    uint2 u = make_uint2(*reinterpret_cast<unsigned*>(&p0),
                         *reinterpret_cast<unsigned*>(&p1));
    *reinterpret_cast<uint2*>(out + (size_t)row * DMv + threadIdx.x * 4) = u;
}

// ---------------------------------------------------------------------------
// fp16 big-tile GEMM: BM=256, BN=128, BK=32, warp tile 64x64, 3-stage.
// EPI 0:+bias  3:raw (split-K partial).
// ---------------------------------------------------------------------------
template <int EPI>
__global__ void __launch_bounds__(256) gemm_big(
    const __half* __restrict__ A, const __half* __restrict__ B,
    const float* __restrict__ bias, float* __restrict__ C,
    int N, int Kd, int lda, size_t partStride)
{
    constexpr int BM = 256, BN = 128, BK = 32;
    constexpr int ASTR = BK + 8, BSTR = BN + 8;
    constexpr int ASZ = BM * ASTR, BSZ = BK * BSTR, STAGE = ASZ + BSZ;

    extern __shared__ __half smem[];
    unsigned sbase = (unsigned)__cvta_generic_to_shared(smem);

    int tid = threadIdx.x, lane = tid & 31, warp = tid >> 5;
    int wm = warp >> 1, wn = warp & 1;
    int bm = blockIdx.y * BM, bn = blockIdx.x * BN;
    int part = blockIdx.z;
    const __half* Ap = A + (size_t)part * Kd;
    const __half* Bp = B + (size_t)part * Kd * N;
    float* Cp = C + (size_t)part * partStride;

    float acc[4][8][4];
    #pragma unroll
    for (int i = 0; i < 4; i++)
        #pragma unroll
        for (int j = 0; j < 8; j++)
            #pragma unroll
            for (int q = 0; q < 4; q++) acc[i][j][q] = 0.f;

    auto issue = [&](int st, int kt) {
        __half* As = smem + st * STAGE;
        __half* Bs = As + ASZ;
        #pragma unroll
        for (int i = 0; i < 4; i++) {
            int li = tid + i * 256;
            int m = li >> 2, c = (li & 3) * 8;
            cp16g(As + m * ASTR + c, Ap + (size_t)(bm + m) * lda + kt + c, true);
        }
        #pragma unroll
        for (int i = 0; i < 2; i++) {
            int li = tid + i * 256;
            int r = li >> 4, c8 = (li & 15) * 8;
            cp16g(Bs + r * BSTR + c8, Bp + (size_t)(kt + r) * N + bn + c8, true);
        }
        asm volatile("cp.async.commit_group;\n" ::: "memory");
    };

    int g = lane >> 3, lr = lane & 7;
    auto compute = [&](int st) {
        unsigned abase = sbase + (st * STAGE) * 2;
        unsigned bbase = abase + ASZ * 2;
        #pragma unroll
        for (int ks = 0; ks < 2; ks++) {
            int k0 = ks * 16;
            unsigned af[4][4];
            #pragma unroll
            for (int mi = 0; mi < 4; mi++) {
                int row = wm * 64 + mi * 16 + (g & 1) * 8 + lr;
                int col = k0 + (g >> 1) * 8;
                ldsm_x4(af[mi][0], af[mi][1], af[mi][2], af[mi][3],
                        abase + (row * ASTR + col) * 2);
            }
            #pragma unroll
            for (int p = 0; p < 4; p++) {
                int row = k0 + (g & 1) * 8 + lr;
                int col = wn * 64 + p * 16 + (g >> 1) * 8;
                unsigned b0, b1, b2, b3;
                ldsm_x4t(b0, b1, b2, b3, bbase + (row * BSTR + col) * 2);
                #pragma unroll
                for (int mi = 0; mi < 4; mi++) {
                    MMA16816(acc[mi][2 * p], af[mi], b0, b1);
                    MMA16816(acc[mi][2 * p + 1], af[mi], b2, b3);
                }
            }
        }
    };

    int nt = Kd / BK;
    issue(0, 0);
    issue(1, BK);
    int st = 0;
    for (int i = 0; i < nt; i++) {
        if (i == nt - 1)
            asm volatile("cp.async.wait_group 0;\n" ::: "memory");
        else
            asm volatile("cp.async.wait_group 1;\n" ::: "memory");
        __syncthreads();
        if (i + 2 < nt) {
            int st2 = st + 2; if (st2 >= 3) st2 -= 3;
            issue(st2, (i + 2) * BK);
        }
        compute(st);
        if (++st == 3) st = 0;
    }

    #pragma unroll
    for (int mi = 0; mi < 4; mi++) {
        int r0 = bm + wm * 64 + mi * 16 + (lane >> 2);
        #pragma unroll
        for (int ni = 0; ni < 8; ni++) {
            int c0 = bn + wn * 64 + ni * 8 + (lane & 3) * 2;
            #pragma unroll
            for (int h = 0; h < 2; h++) {
                int rr = r0 + h * 8;
                float v0 = acc[mi][ni][h * 2 + 0];
                float v1 = acc[mi][ni][h * 2 + 1];
                if (EPI != 3) { v0 += bias[c0]; v1 += bias[c0 + 1]; }
                *reinterpret_cast<float2*>(&Cp[(size_t)rr * N + c0]) = make_float2(v0, v1);
            }
        }
    }
}

// ---------------------------------------------------------------------------
// fp16 medium GEMM: BM=128, BN=128, BK=32, warp tile 32x64, 3-stage.
// EPI: +bias, softplus (dup GEMM).
// ---------------------------------------------------------------------------
__global__ void __launch_bounds__(256) gemm_med(
    const __half* __restrict__ A, const __half* __restrict__ B,
    const float* __restrict__ bias, float* __restrict__ C,
    int N, int Kd, int lda)
{
    constexpr int BM = 128, BN = 128, BK = 32;
    constexpr int ASTR = BK + 8, BSTR = BN + 8;
    constexpr int ASZ = BM * ASTR, BSZ = BK * BSTR, STAGE = ASZ + BSZ;

    extern __shared__ __half smem[];
    unsigned sbase = (unsigned)__cvta_generic_to_shared(smem);

    int tid = threadIdx.x, lane = tid & 31, warp = tid >> 5;
    int wm = warp >> 1, wn = warp & 1;
    int bm = blockIdx.y * BM, bn = blockIdx.x * BN;

    const __half* Ap_ = A;      // declared BEFORE lambdas (capture fix)
    const __half* Bp_ = B;

    float acc[2][8][4];
    #pragma unroll
    for (int i = 0; i < 2; i++)
        #pragma unroll
        for (int j = 0; j < 8; j++)
            #pragma unroll
            for (int q = 0; q < 4; q++) acc[i][j][q] = 0.f;

    auto issue = [&](int st, int kt) {
        __half* As = smem + st * STAGE;
        __half* Bs = As + ASZ;
        #pragma unroll
        for (int i = 0; i < 2; i++) {
            int li = tid + i * 256;
            int m = li >> 2, c = (li & 3) * 8;
            cp16g(As + m * ASTR + c, Ap_ + (size_t)(bm + m) * lda + kt + c, true);
        }
        #pragma unroll
        for (int i = 0; i < 2; i++) {
            int li = tid + i * 256;
            int r = li >> 4, c8 = (li & 15) * 8;
            cp16g(Bs + r * BSTR + c8, Bp_ + (size_t)(kt + r) * N + bn + c8, true);
        }
        asm volatile("cp.async.commit_group;\n" ::: "memory");
    };

    int g = lane >> 3, lr = lane & 7;
    auto compute = [&](int st) {
        unsigned abase = sbase + (st * STAGE) * 2;
        unsigned bbase = abase + ASZ * 2;
        #pragma unroll
        for (int ks = 0; ks < 2; ks++) {
            int k0 = ks * 16;
            unsigned af[2][4];
            #pragma unroll
            for (int mi = 0; mi < 2; mi++) {
                int row = wm * 32 + mi * 16 + (g & 1) * 8 + lr;
                int col = k0 + (g >> 1) * 8;
                ldsm_x4(af[mi][0], af[mi][1], af[mi][2], af[mi][3],
                        abase + (row * ASTR + col) * 2);
            }
            #pragma unroll
            for (int p = 0; p < 4; p++) {
                int row = k0 + (g & 1) * 8 + lr;
                int col = wn * 64 + p * 16 + (g >> 1) * 8;
                unsigned b0, b1, b2, b3;
                ldsm_x4t(b0, b1, b2, b3, bbase + (row * BSTR + col) * 2);
                #pragma unroll
                for (int mi = 0; mi < 2; mi++) {
                    MMA16816(acc[mi][2 * p], af[mi], b0, b1);
                    MMA16816(acc[mi][2 * p + 1], af[mi], b2, b3);
                }
            }
        }
    };

    int nt = Kd / BK;
    issue(0, 0);
    issue(1, BK);
    int st = 0;
    for (int i = 0; i < nt; i++) {
        if (i == nt - 1)
            asm volatile("cp.async.wait_group 0;\n" ::: "memory");
        else
            asm volatile("cp.async.wait_group 1;\n" ::: "memory");
        __syncthreads();
        if (i + 2 < nt) {
            int st2 = st + 2; if (st2 >= 3) st2 -= 3;
            issue(st2, (i + 2) * BK);
        }
        compute(st);
        if (++st == 3) st = 0;
    }

    #pragma unroll
    for (int mi = 0; mi < 2; mi++) {
        int r0 = bm + wm * 32 + mi * 16 + (lane >> 2);
        #pragma unroll
        for (int ni = 0; ni < 8; ni++) {
            int c0 = bn + wn * 64 + ni * 8 + (lane & 3) * 2;
            #pragma unroll
            for (int h = 0; h < 2; h++) {
                int rr = r0 + h * 8;
                float v0 = acc[mi][ni][h * 2 + 0] + bias[c0];
                float v1 = acc[mi][ni][h * 2 + 1] + bias[c0 + 1];
                v0 = (v0 > 20.0f) ? v0 : log1pf(__expf(v0));
                v1 = (v1 > 20.0f) ? v1 : log1pf(__expf(v1));
                *reinterpret_cast<float2*>(&C[(size_t)rr * N + c0]) = make_float2(v0, v1);
            }
        }
    }
}

// ---------------------------------------------------------------------------
// fp16 128x64 GEMM (dbc split-K partials). Warp tile 32x32.
// ---------------------------------------------------------------------------
__global__ void __launch_bounds__(256) gemm_dbc(
    const __half* __restrict__ A, const __half* __restrict__ B,
    float* __restrict__ C, int N, int Kd, int lda, size_t partStride)
{
    constexpr int BM = 128, BN = 64, BK = 32;
    constexpr int ASTR = BK + 8, BSTR = BN + 8;
    constexpr int ASZ = BM * ASTR, BSZ = BK * BSTR, STAGE = ASZ + BSZ;

    extern __shared__ __half smem[];
    unsigned sbase = (unsigned)__cvta_generic_to_shared(smem);

    int tid = threadIdx.x, lane = tid & 31, warp = tid >> 5;
    int wm = warp >> 1, wn = warp & 1;
    int bm = blockIdx.y * BM, bn = blockIdx.x * BN;
    int part = blockIdx.z;
    const __half* Ap = A + (size_t)part * Kd;
    const __half* Bp = B + (size_t)part * Kd * N;
    float* Cp = C + (size_t)part * partStride;

    float acc[2][4][4];
    #pragma unroll
    for (int i = 0; i < 2; i++)
        #pragma unroll
        for (int j = 0; j < 4; j++)
            #pragma unroll
            for (int q = 0; q < 4; q++) acc[i][j][q] = 0.f;

    auto issue = [&](int st, int kt) {
        __half* As = smem + st * STAGE;
        __half* Bs = As + ASZ;
        #pragma unroll
        for (int i = 0; i < 2; i++) {
            int li = tid + i * 256;
            int m = li >> 2, c = (li & 3) * 8;
            cp16g(As + m * ASTR + c, Ap + (size_t)(bm + m) * lda + kt + c, true);
        }
        if (tid < 256) {
            int r = tid >> 3, c8 = (tid & 7) * 8;
            cp16g(Bs + r * BSTR + c8, Bp + (size_t)(kt + r) * N + bn + c8,
                  (bn + c8) < N);
        }
        asm volatile("cp.async.commit_group;\n" ::: "memory");
    };

    int g = lane >> 3, lr = lane & 7;
    auto compute = [&](int st) {
        unsigned abase = sbase + (st * STAGE) * 2;
        unsigned bbase = abase + ASZ * 2;
        #pragma unroll
        for (int ks = 0; ks < 2; ks++) {
            int k0 = ks * 16;
            unsigned af[2][4];
            #pragma unroll
            for (int mi = 0; mi < 2; mi++) {
                int row = wm * 32 + mi * 16 + (g & 1) * 8 + lr;
                int col = k0 + (g >> 1) * 8;
                ldsm_x4(af[mi][0], af[mi][1], af[mi][2], af[mi][3],
                        abase + (row * ASTR + col) * 2);
            }
            #pragma unroll
            for (int p = 0; p < 2; p++) {
                int row = k0 + (g & 1) * 8 + lr;
                int col = wn * 32 + p * 16 + (g >> 1) * 8;
                unsigned b0, b1, b2, b3;
                ldsm_x4t(b0, b1, b2, b3, bbase + (row * BSTR + col) * 2);
                #pragma unroll
                for (int mi = 0; mi < 2; mi++) {
                    MMA16816(acc[mi][2 * p], af[mi], b0, b1);
                    MMA16816(acc[mi][2 * p + 1], af[mi], b2, b3);
                }
            }
        }
    };

    int nt = Kd / BK;
    issue(0, 0);
    issue(1, BK);
    int st = 0;
    for (int i = 0; i < nt; i++) {
        if (i == nt - 1)
            asm volatile("cp.async.wait_group 0;\n" ::: "memory");
        else
            asm volatile("cp.async.wait_group 1;\n" ::: "memory");
        __syncthreads();
        if (i + 2 < nt) {
            int st2 = st + 2; if (st2 >= 3) st2 -= 3;
            issue(st2, (i + 2) * BK);
        }
        compute(st);
        if (++st == 3) st = 0;
    }

    #pragma unroll
    for (int mi = 0; mi < 2; mi++) {
        int r0 = bm + wm * 32 + mi * 16 + (lane >> 2);
        #pragma unroll
        for (int ni = 0; ni < 4; ni++) {
            int c0 = bn + wn * 32 + ni * 8 + (lane & 3) * 2;
            if (c0 >= N) continue;
            #pragma unroll
            for (int h = 0; h < 2; h++) {
                int rr = r0 + h * 8;
                *reinterpret_cast<float2*>(&Cp[(size_t)rr * N + c0]) =
                    make_float2(acc[mi][ni][h * 2 + 0], acc[mi][ni][h * 2 + 1]);
            }
        }
    }
}

// ---------------------------------------------------------------------------
// Reduces
// ---------------------------------------------------------------------------
__global__ void __launch_bounds__(256) reduce8_k(
    const float* __restrict__ P, const float* __restrict__ bias,
    float* __restrict__ C, __half* __restrict__ Dh)
{
    const size_t PS = (size_t)NROWS * 160;
    size_t i = (size_t)blockIdx.x * 256 + threadIdx.x;
    int col = (int)(i % 160);
    size_t row = i / 160;
    float v = bias[col];
    #pragma unroll
    for (int p = 0; p < 8; p++) v += P[i + p * PS];
    if (col < 128) Dh[row * 128 + col] = __float2half(v);
    else           C[i] = v;
}

// out = P0+P1+P2+P3 + bias + residual
__global__ void __launch_bounds__(256) reduce4_out_k(
    const float* __restrict__ P, const float* __restrict__ bias,
    const float* __restrict__ x, float* __restrict__ C)
{
    const size_t PS = (size_t)NROWS * DMv;
    size_t i = ((size_t)blockIdx.x * 256 + threadIdx.x) * 4;
    float4 a = *reinterpret_cast<const float4*>(&P[i]);
    float4 b = *reinterpret_cast<const float4*>(&P[i + PS]);
    float4 c = *reinterpret_cast<const float4*>(&P[i + 2 * PS]);
    float4 d = *reinterpret_cast<const float4*>(&P[i + 3 * PS]);
    float4 r = *reinterpret_cast<const float4*>(&x[i]);
    const float4 bv = *reinterpret_cast<const float4*>(&bias[i % DMv]);
    float4 o;
    o.x = a.x + b.x + c.x + d.x + r.x + bv.x;
    o.y = a.y + b.y + c.y + d.y + r.y + bv.y;
    o.z = a.z + b.z + c.z + d.z + r.z + bv.z;
    o.w = a.w + b.w + c.w + d.w + r.w + bv.w;
    *reinterpret_cast<float4*>(&C[i]) = o;
}

// ---------------------------------------------------------------------------
// Depthwise causal conv (K=4) + SiLU -> x1c (float) + x1cp (half)
// ---------------------------------------------------------------------------
__global__ void __launch_bounds__(256) conv_silu_k(
    const float* __restrict__ proj, const float* __restrict__ cw,
    const float* __restrict__ cb, float* __restrict__ out, __half* __restrict__ outp)
{
    int d = blockIdx.x * 256 + threadIdx.x;
    int row = blockIdx.y;
    int t = row & (Tv - 1);
    int b = row >> 10;
    float4 w = *reinterpret_cast<const float4*>(cw + (size_t)d * 4);
    float acc = cb[d];
    const float* base = proj + (size_t)(b * Tv) * 4096 + d;
    if (t >= 3) acc = fmaf(base[(size_t)(t - 3) * 4096], w.x, acc);
    if (t >= 2) acc = fmaf(base[(size_t)(t - 2) * 4096], w.y, acc);
    if (t >= 1) acc = fmaf(base[(size_t)(t - 1) * 4096], w.z, acc);
    acc = fmaf(base[(size_t)t * 4096], w.w, acc);
    float sv = silu_f(acc);
    out[(size_t)row * Dv + d] = sv;
    outp[(size_t)row * Dv + d] = __float2half(sv);
}

// ---------------------------------------------------------------------------
// Selective scan, smem-staged. ymod written half.
// ---------------------------------------------------------------------------
__global__ void __launch_bounds__(256) scan_k(
    const float* __restrict__ dbc, const float* __restrict__ delta,
    const float* __restrict__ x1c, const float* __restrict__ proj,
    const float* __restrict__ A_log, __half* __restrict__ ymod)
{
    __shared__ float Bs[128][16];
    __shared__ float Cs[128][16];
    __shared__ float De[128][16];
    __shared__ float Xs[128][16];
    __shared__ float Ys[128][16];
    int tid = threadIdx.x;
    int n = tid & 15, grp = tid >> 4;
    int b = blockIdx.y;
    int d0 = blockIdx.x * 16;
    float An = -__expf(A_log[(size_t)(d0 + grp) * NSTv + n]);
    float h = 0.f;

    for (int c = 0; c < 8; c++) {
        __syncthreads();
        int t0 = c * 128;
        for (int idx = tid; idx < 2048; idx += 256) {
            int tl = idx >> 4, nn = idx & 15;
            size_t r = (size_t)(b * Tv + t0 + tl) * 160;
            Bs[tl][nn] = dbc[r + 128 + nn];
            Cs[tl][nn] = dbc[r + 144 + nn];
            size_t rr = (size_t)(b * Tv + t0 + tl) * Dv + d0 + nn;
            De[tl][nn] = delta[rr];
            Xs[tl][nn] = x1c[rr];
        }
        __syncthreads();
        #pragma unroll 8
        for (int tl = 0; tl < 128; tl++) {
            float de = De[tl][grp];
            float xx = Xs[tl][grp];
            float a = __expf(de * An);
            h = fmaf(a, h, de * Bs[tl][n] * xx);
            float p = h * Cs[tl][n];
            p += __shfl_xor_sync(0xffffffffu, p, 8);
            p += __shfl_xor_sync(0xffffffffu, p, 4);
            p += __shfl_xor_sync(0xffffffffu, p, 2);
            p += __shfl_xor_sync(0xffffffffu, p, 1);
            if (n == 0) Ys[tl][grp] = p;
        }
        __syncthreads();
        for (int idx = tid; idx < 2048; idx += 256) {
            int tl = idx >> 4, dl2 = idx & 15;
            int row = b * Tv + t0 + tl;
            float g = proj[(size_t)row * 4096 + 2048 + d0 + dl2];
            ymod[(size_t)row * Dv + d0 + dl2] = __float2half(Ys[tl][dl2] * silu_f(g));
        }
    }
}

// ---------------------------------------------------------------------------
extern "C" void kernel_launch(void* const* d_in, const int* in_sizes, int n_in,
                              void* d_out, int out_size)
{
    const float* x      = (const float*)d_in[0];
    const float* rms_w  = (const float*)d_in[1];
    const float* in_W   = (const float*)d_in[2];
    const float* in_b   = (const float*)d_in[3];
    const float* conv_w = (const float*)d_in[4];
    const float* conv_b = (const float*)d_in[5];
    const float* A_log  = (const float*)d_in[6];
    const float* dbc_W  = (const float*)d_in[7];
    const float* dbc_b  = (const float*)d_in[8];
    const float* dup_W  = (const float*)d_in[9];
    const float* dup_b  = (const float*)d_in[10];
    const float* out_W  = (const float*)d_in[11];
    const float* out_b  = (const float*)d_in[12];
    float* out = (float*)d_out;

    float* S = nullptr;
    cudaGetSymbolAddress((void**)&S, g_scratch);
    __half* Hh    = (__half*)(S + OFF_H);
    __half* X1cp  = (__half*)(S + OFF_X1CP);
    __half* Dh    = (__half*)(S + OFF_DELTAH);
    __half* Ymodh = (__half*)(S + OFF_YMOD);
    __half* Win   = (__half*)(S + OFF_WINR);
    __half* Wdbc  = (__half*)(S + OFF_WDBCR);
    __half* Wdup  = (__half*)(S + OFF_WDUPR);
    __half* Wout  = (__half*)(S + OFF_WOUTR);

    const int SMBIG = 3 * (256 * 40 + 32 * 136) * 2;   // 87552 B
    const int SMMED = 3 * (128 * 40 + 32 * 136) * 2;   // 56832 B
    const int SMDBC = 3 * (128 * 40 + 32 * 72) * 2;    // 44544 B
    cudaFuncSetAttribute(gemm_big<0>, cudaFuncAttributeMaxDynamicSharedMemorySize, SMBIG);
    cudaFuncSetAttribute(gemm_big<3>, cudaFuncAttributeMaxDynamicSharedMemorySize, SMBIG);
    cudaFuncSetAttribute(gemm_med,    cudaFuncAttributeMaxDynamicSharedMemorySize, SMMED);
    cudaFuncSetAttribute(gemm_dbc,    cudaFuncAttributeMaxDynamicSharedMemorySize, SMDBC);

    // 0. Convert all weights to half (one launch)
    convw_k<<<(WSZ1 + WSZ2 + WSZ3 + WSZ4) / 1024, 256>>>(
        in_W, dbc_W, dup_W, out_W, Win, Wdbc, Wdup, Wout);

    // 1. RMSNorm -> h (half)
    rmsnorm_k<<<NROWS, 256>>>(x, rms_w, Hh);

    // 2. in_proj: (2048x1024)@(1024x4096)   grid 256
    gemm_big<0><<<dim3(32, 8, 1), 256, SMBIG>>>(
        Hh, Win, in_b, S + OFF_PROJ, 4096, 1024, 1024, 0);

    // 3. depthwise conv + SiLU
    conv_silu_k<<<dim3(Dv / 256, NROWS), 256>>>(
        S + OFF_PROJ, conv_w, conv_b, S + OFF_X1C, X1cp);

    // 4. dbc: split-K x8 + reduce     grid 384
    gemm_dbc<<<dim3(3, 16, 8), 256, SMDBC>>>(
        X1cp, Wdbc, S + OFF_DBCP, 160, 256, 2048, (size_t)NROWS * 160);
    reduce8_k<<<(NROWS * 160) / 256, 256>>>(S + OFF_DBCP, dbc_b, S + OFF_DBC, Dh);

    // 5. delta up-proj + softplus     grid 256
    gemm_med<<<dim3(16, 16), 256, SMMED>>>(
        Dh, Wdup, dup_b, S + OFF_DELTA, 2048, 128, 128);

    // 6. selective scan + silu(g) gating
    scan_k<<<dim3(Dv / 16, 2), 256>>>(
        S + OFF_DBC, S + OFF_DELTA, S + OFF_X1C, S + OFF_PROJ, A_log, Ymodh);

    // 7. out_proj split-K x4 + fused reduce   grid 256
    gemm_big<3><<<dim3(8, 8, 4), 256, SMBIG>>>(
        Ymodh, Wout, nullptr, S + OFF_OUTP, 1024, 512, 2048,
        (size_t)NROWS * DMv);
    reduce4_out_k<<<(NROWS * DMv) / 1024, 256>>>(S + OFF_OUTP, out_b, x, out);
}

// round 17
// speedup vs baseline: 1.3966x; 1.0879x over previous
#include <cuda_runtime.h>
#include <cuda_fp16.h>
#include <cstdint>

// ---------------------------------------------------------------------------
// MambaBlock: B=2, T=1024, DM=1024, D=2048, N=16, K=4, DTR=128
// Round 17: round-16 base + PROJ intermediate stored fp16 (in_proj writes
// half, conv + scan-gate read half) and t-tiled conv (8 outputs / thread,
// 11-tap window -> 1.4 loads/output).
// ---------------------------------------------------------------------------

#define DMv   1024
#define Dv    2048
#define Tv    1024
#define NROWS 2048
#define NSTv  16

// Scratch layout (float units)
#define OFF_H      0u          // half [2048*1024]
#define OFF_PROJH  1048576u    // half [2048*4096]
#define OFF_X1C    5242880u    // float [2048*2048] (scan)
#define OFF_X1CP   9437184u    // half  [2048*2048] (dbc A)
#define OFF_DBC    11534336u   // float [2048*160]
#define OFF_DELTAH 11862016u   // half  [2048*128]
#define OFF_DELTA  11993088u   // float [2048*2048] (scan)
#define OFF_YMOD   16187392u   // half  [2048*2048]
#define OFF_DBCP   18284544u   // float [8*2048*160]
#define OFF_OUTP   20905984u   // float [4*2048*1024]
#define OFF_WINR   29294592u   // half in_W
#define OFF_WDBCR  31391744u   // half dbc_W
#define OFF_WDUPR  31555584u   // half dup_W
#define OFF_WOUTR  31686656u   // half out_W
#define SCRATCH_FLOATS 32735232u

__device__ __align__(128) float g_scratch[SCRATCH_FLOATS];

__device__ __forceinline__ float silu_f(float v) {
    return v * (1.0f / (1.0f + __expf(-v)));
}
__device__ __forceinline__ void cp16g(void* dst, const void* src, bool p) {
    unsigned d = (unsigned)__cvta_generic_to_shared(dst);
    int sz = p ? 16 : 0;
    asm volatile("cp.async.cg.shared.global [%0], [%1], 16, %2;\n"
                 :: "r"(d), "l"(src), "r"(sz));
}
__device__ __forceinline__ void ldsm_x4(unsigned& r0, unsigned& r1,
                                        unsigned& r2, unsigned& r3, unsigned a) {
    asm volatile("ldmatrix.sync.aligned.m8n8.x4.shared.b16 {%0,%1,%2,%3}, [%4];"
                 : "=r"(r0), "=r"(r1), "=r"(r2), "=r"(r3) : "r"(a));
}
__device__ __forceinline__ void ldsm_x4t(unsigned& r0, unsigned& r1,
                                         unsigned& r2, unsigned& r3, unsigned a) {
    asm volatile("ldmatrix.sync.aligned.m8n8.x4.trans.shared.b16 {%0,%1,%2,%3}, [%4];"
                 : "=r"(r0), "=r"(r1), "=r"(r2), "=r"(r3) : "r"(a));
}
#define MMA16816(acc, a, b0, b1) \
    asm volatile( \
        "mma.sync.aligned.m16n8k16.row.col.f32.f16.f16.f32 " \
        "{%0,%1,%2,%3}, {%4,%5,%6,%7}, {%8,%9}, {%0,%1,%2,%3};\n" \
        : "+f"((acc)[0]), "+f"((acc)[1]), "+f"((acc)[2]), "+f"((acc)[3]) \
        : "r"((a)[0]), "r"((a)[1]), "r"((a)[2]), "r"((a)[3]), "r"(b0), "r"(b1))

// Typed pair-store for GEMM epilogues
__device__ __forceinline__ void st2(float* p, float v0, float v1) {
    *reinterpret_cast<float2*>(p) = make_float2(v0, v1);
}
__device__ __forceinline__ void st2(__half* p, float v0, float v1) {
    *reinterpret_cast<__half2*>(p) = __floats2half2_rn(v0, v1);
}

// ---------------------------------------------------------------------------
// Merged weight convert: all 4 weight matrices float->half in one launch.
// ---------------------------------------------------------------------------
#define WSZ1 4194304u
#define WSZ2 327680u
#define WSZ3 262144u
#define WSZ4 2097152u
__global__ void __launch_bounds__(256) convw_k(
    const float* __restrict__ inW, const float* __restrict__ dbcW,
    const float* __restrict__ dupW, const float* __restrict__ outW,
    __half* __restrict__ oin, __half* __restrict__ odbc,
    __half* __restrict__ odup, __half* __restrict__ oout)
{
    size_t i = ((size_t)blockIdx.x * 256 + threadIdx.x) * 4;
    const float* src; __half* dst; size_t off;
    if (i < WSZ1)                     { src = inW;  dst = oin;  off = i; }
    else if (i < WSZ1 + WSZ2)         { src = dbcW; dst = odbc; off = i - WSZ1; }
    else if (i < WSZ1 + WSZ2 + WSZ3)  { src = dupW; dst = odup; off = i - WSZ1 - WSZ2; }
    else                              { src = outW; dst = oout; off = i - WSZ1 - WSZ2 - WSZ3; }
    float4 v = *reinterpret_cast<const float4*>(&src[off]);
    __half2 p0 = __floats2half2_rn(v.x, v.y);
    __half2 p1 = __floats2half2_rn(v.z, v.w);
    uint2 u = make_uint2(*reinterpret_cast<unsigned*>(&p0),
                         *reinterpret_cast<unsigned*>(&p1));
    *reinterpret_cast<uint2*>(dst + off) = u;
}

// ---------------------------------------------------------------------------
// RMSNorm -> h (half)
// ---------------------------------------------------------------------------
__global__ void __launch_bounds__(256) rmsnorm_k(
    const float* __restrict__ x, const float* __restrict__ w, __half* __restrict__ out)
{
    int row = blockIdx.x;
    const float4* xr = reinterpret_cast<const float4*>(x + (size_t)row * DMv);
    float4 v = xr[threadIdx.x];
    float s = v.x * v.x + v.y * v.y + v.z * v.z + v.w * v.w;
    #pragma unroll
    for (int o = 16; o; o >>= 1) s += __shfl_xor_sync(0xffffffffu, s, o);
    __shared__ float ws[8];
    if ((threadIdx.x & 31) == 0) ws[threadIdx.x >> 5] = s;
    __syncthreads();
    float tot = 0.f;
    #pragma unroll
    for (int i = 0; i < 8; i++) tot += ws[i];
    float scale = rsqrtf(tot * (1.0f / (float)DMv) + 1e-6f);
    float4 wv = reinterpret_cast<const float4*>(w)[threadIdx.x];
    __half2 p0 = __floats2half2_rn(v.x * scale * wv.x, v.y * scale * wv.y);
    __half2 p1 = __floats2half2_rn(v.z * scale * wv.z, v.w * scale * wv.w);
    uint2 u = make_uint2(*reinterpret_cast<unsigned*>(&p0),
                         *reinterpret_cast<unsigned*>(&p1));
    *reinterpret_cast<uint2*>(out + (size_t)row * DMv + threadIdx.x * 4) = u;
}

// ---------------------------------------------------------------------------
// fp16 big-tile GEMM: BM=256, BN=128, BK=32, warp tile 64x64, 3-stage.
// TO = output type (float or __half). EPI 0:+bias  3:raw (split-K partial).
// ---------------------------------------------------------------------------
template <int EPI, typename TO>
__global__ void __launch_bounds__(256) gemm_big(
    const __half* __restrict__ A, const __half* __restrict__ B,
    const float* __restrict__ bias, TO* __restrict__ C,
    int N, int Kd, int lda, size_t partStride)
{
    constexpr int BM = 256, BN = 128, BK = 32;
    constexpr int ASTR = BK + 8, BSTR = BN + 8;
    constexpr int ASZ = BM * ASTR, BSZ = BK * BSTR, STAGE = ASZ + BSZ;

    extern __shared__ __half smem[];
    unsigned sbase = (unsigned)__cvta_generic_to_shared(smem);

    int tid = threadIdx.x, lane = tid & 31, warp = tid >> 5;
    int wm = warp >> 1, wn = warp & 1;
    int bm = blockIdx.y * BM, bn = blockIdx.x * BN;
    int part = blockIdx.z;
    const __half* Ap = A + (size_t)part * Kd;
    const __half* Bp = B + (size_t)part * Kd * N;
    TO* Cp = C + (size_t)part * partStride;

    float acc[4][8][4];
    #pragma unroll
    for (int i = 0; i < 4; i++)
        #pragma unroll
        for (int j = 0; j < 8; j++)
            #pragma unroll
            for (int q = 0; q < 4; q++) acc[i][j][q] = 0.f;

    auto issue = [&](int st, int kt) {
        __half* As = smem + st * STAGE;
        __half* Bs = As + ASZ;
        #pragma unroll
        for (int i = 0; i < 4; i++) {
            int li = tid + i * 256;
            int m = li >> 2, c = (li & 3) * 8;
            cp16g(As + m * ASTR + c, Ap + (size_t)(bm + m) * lda + kt + c, true);
        }
        #pragma unroll
        for (int i = 0; i < 2; i++) {
            int li = tid + i * 256;
            int r = li >> 4, c8 = (li & 15) * 8;
            cp16g(Bs + r * BSTR + c8, Bp + (size_t)(kt + r) * N + bn + c8, true);
        }
        asm volatile("cp.async.commit_group;\n" ::: "memory");
    };

    int g = lane >> 3, lr = lane & 7;
    auto compute = [&](int st) {
        unsigned abase = sbase + (st * STAGE) * 2;
        unsigned bbase = abase + ASZ * 2;
        #pragma unroll
        for (int ks = 0; ks < 2; ks++) {
            int k0 = ks * 16;
            unsigned af[4][4];
            #pragma unroll
            for (int mi = 0; mi < 4; mi++) {
                int row = wm * 64 + mi * 16 + (g & 1) * 8 + lr;
                int col = k0 + (g >> 1) * 8;
                ldsm_x4(af[mi][0], af[mi][1], af[mi][2], af[mi][3],
                        abase + (row * ASTR + col) * 2);
            }
            #pragma unroll
            for (int p = 0; p < 4; p++) {
                int row = k0 + (g & 1) * 8 + lr;
                int col = wn * 64 + p * 16 + (g >> 1) * 8;
                unsigned b0, b1, b2, b3;
                ldsm_x4t(b0, b1, b2, b3, bbase + (row * BSTR + col) * 2);
                #pragma unroll
                for (int mi = 0; mi < 4; mi++) {
                    MMA16816(acc[mi][2 * p], af[mi], b0, b1);
                    MMA16816(acc[mi][2 * p + 1], af[mi], b2, b3);
                }
            }
        }
    };

    int nt = Kd / BK;
    issue(0, 0);
    issue(1, BK);
    int st = 0;
    for (int i = 0; i < nt; i++) {
        if (i == nt - 1)
            asm volatile("cp.async.wait_group 0;\n" ::: "memory");
        else
            asm volatile("cp.async.wait_group 1;\n" ::: "memory");
        __syncthreads();
        if (i + 2 < nt) {
            int st2 = st + 2; if (st2 >= 3) st2 -= 3;
            issue(st2, (i + 2) * BK);
        }
        compute(st);
        if (++st == 3) st = 0;
    }

    #pragma unroll
    for (int mi = 0; mi < 4; mi++) {
        int r0 = bm + wm * 64 + mi * 16 + (lane >> 2);
        #pragma unroll
        for (int ni = 0; ni < 8; ni++) {
            int c0 = bn + wn * 64 + ni * 8 + (lane & 3) * 2;
            #pragma unroll
            for (int h = 0; h < 2; h++) {
                int rr = r0 + h * 8;
                float v0 = acc[mi][ni][h * 2 + 0];
                float v1 = acc[mi][ni][h * 2 + 1];
                if (EPI != 3) { v0 += bias[c0]; v1 += bias[c0 + 1]; }
                st2(&Cp[(size_t)rr * N + c0], v0, v1);
            }
        }
    }
}

// ---------------------------------------------------------------------------
// fp16 medium GEMM: BM=128, BN=128, BK=32, warp tile 32x64, 3-stage.
// EPI: +bias, softplus (dup GEMM), float out.
// ---------------------------------------------------------------------------
__global__ void __launch_bounds__(256) gemm_med(
    const __half* __restrict__ A, const __half* __restrict__ B,
    const float* __restrict__ bias, float* __restrict__ C,
    int N, int Kd, int lda)
{
    constexpr int BM = 128, BN = 128, BK = 32;
    constexpr int ASTR = BK + 8, BSTR = BN + 8;
    constexpr int ASZ = BM * ASTR, BSZ = BK * BSTR, STAGE = ASZ + BSZ;

    extern __shared__ __half smem[];
    unsigned sbase = (unsigned)__cvta_generic_to_shared(smem);

    int tid = threadIdx.x, lane = tid & 31, warp = tid >> 5;
    int wm = warp >> 1, wn = warp & 1;
    int bm = blockIdx.y * BM, bn = blockIdx.x * BN;

    const __half* Ap_ = A;
    const __half* Bp_ = B;

    float acc[2][8][4];
    #pragma unroll
    for (int i = 0; i < 2; i++)
        #pragma unroll
        for (int j = 0; j < 8; j++)
            #pragma unroll
            for (int q = 0; q < 4; q++) acc[i][j][q] = 0.f;

    auto issue = [&](int st, int kt) {
        __half* As = smem + st * STAGE;
        __half* Bs = As + ASZ;
        #pragma unroll
        for (int i = 0; i < 2; i++) {
            int li = tid + i * 256;
            int m = li >> 2, c = (li & 3) * 8;
            cp16g(As + m * ASTR + c, Ap_ + (size_t)(bm + m) * lda + kt + c, true);
        }
        #pragma unroll
        for (int i = 0; i < 2; i++) {
            int li = tid + i * 256;
            int r = li >> 4, c8 = (li & 15) * 8;
            cp16g(Bs + r * BSTR + c8, Bp_ + (size_t)(kt + r) * N + bn + c8, true);
        }
        asm volatile("cp.async.commit_group;\n" ::: "memory");
    };

    int g = lane >> 3, lr = lane & 7;
    auto compute = [&](int st) {
        unsigned abase = sbase + (st * STAGE) * 2;
        unsigned bbase = abase + ASZ * 2;
        #pragma unroll
        for (int ks = 0; ks < 2; ks++) {
            int k0 = ks * 16;
            unsigned af[2][4];
            #pragma unroll
            for (int mi = 0; mi < 2; mi++) {
                int row = wm * 32 + mi * 16 + (g & 1) * 8 + lr;
                int col = k0 + (g >> 1) * 8;
                ldsm_x4(af[mi][0], af[mi][1], af[mi][2], af[mi][3],
                        abase + (row * ASTR + col) * 2);
            }
            #pragma unroll
            for (int p = 0; p < 4; p++) {
                int row = k0 + (g & 1) * 8 + lr;
                int col = wn * 64 + p * 16 + (g >> 1) * 8;
                unsigned b0, b1, b2, b3;
                ldsm_x4t(b0, b1, b2, b3, bbase + (row * BSTR + col) * 2);
                #pragma unroll
                for (int mi = 0; mi < 2; mi++) {
                    MMA16816(acc[mi][2 * p], af[mi], b0, b1);
                    MMA16816(acc[mi][2 * p + 1], af[mi], b2, b3);
                }
            }
        }
    };

    int nt = Kd / BK;
    issue(0, 0);
    issue(1, BK);
    int st = 0;
    for (int i = 0; i < nt; i++) {
        if (i == nt - 1)
            asm volatile("cp.async.wait_group 0;\n" ::: "memory");
        else
            asm volatile("cp.async.wait_group 1;\n" ::: "memory");
        __syncthreads();
        if (i + 2 < nt) {
            int st2 = st + 2; if (st2 >= 3) st2 -= 3;
            issue(st2, (i + 2) * BK);
        }
        compute(st);
        if (++st == 3) st = 0;
    }

    #pragma unroll
    for (int mi = 0; mi < 2; mi++) {
        int r0 = bm + wm * 32 + mi * 16 + (lane >> 2);
        #pragma unroll
        for (int ni = 0; ni < 8; ni++) {
            int c0 = bn + wn * 64 + ni * 8 + (lane & 3) * 2;
            #pragma unroll
            for (int h = 0; h < 2; h++) {
                int rr = r0 + h * 8;
                float v0 = acc[mi][ni][h * 2 + 0] + bias[c0];
                float v1 = acc[mi][ni][h * 2 + 1] + bias[c0 + 1];
                v0 = (v0 > 20.0f) ? v0 : log1pf(__expf(v0));
                v1 = (v1 > 20.0f) ? v1 : log1pf(__expf(v1));
                *reinterpret_cast<float2*>(&C[(size_t)rr * N + c0]) = make_float2(v0, v1);
            }
        }
    }
}

// ---------------------------------------------------------------------------
// fp16 128x64 GEMM (dbc split-K partials). Warp tile 32x32.
// ---------------------------------------------------------------------------
__global__ void __launch_bounds__(256) gemm_dbc(
    const __half* __restrict__ A, const __half* __restrict__ B,
    float* __restrict__ C, int N, int Kd, int lda, size_t partStride)
{
    constexpr int BM = 128, BN = 64, BK = 32;
    constexpr int ASTR = BK + 8, BSTR = BN + 8;
    constexpr int ASZ = BM * ASTR, BSZ = BK * BSTR, STAGE = ASZ + BSZ;

    extern __shared__ __half smem[];
    unsigned sbase = (unsigned)__cvta_generic_to_shared(smem);

    int tid = threadIdx.x, lane = tid & 31, warp = tid >> 5;
    int wm = warp >> 1, wn = warp & 1;
    int bm = blockIdx.y * BM, bn = blockIdx.x * BN;
    int part = blockIdx.z;
    const __half* Ap = A + (size_t)part * Kd;
    const __half* Bp = B + (size_t)part * Kd * N;
    float* Cp = C + (size_t)part * partStride;

    float acc[2][4][4];
    #pragma unroll
    for (int i = 0; i < 2; i++)
        #pragma unroll
        for (int j = 0; j < 4; j++)
            #pragma unroll
            for (int q = 0; q < 4; q++) acc[i][j][q] = 0.f;

    auto issue = [&](int st, int kt) {
        __half* As = smem + st * STAGE;
        __half* Bs = As + ASZ;
        #pragma unroll
        for (int i = 0; i < 2; i++) {
            int li = tid + i * 256;
            int m = li >> 2, c = (li & 3) * 8;
            cp16g(As + m * ASTR + c, Ap + (size_t)(bm + m) * lda + kt + c, true);
        }
        if (tid < 256) {
            int r = tid >> 3, c8 = (tid & 7) * 8;
            cp16g(Bs + r * BSTR + c8, Bp + (size_t)(kt + r) * N + bn + c8,
                  (bn + c8) < N);
        }
        asm volatile("cp.async.commit_group;\n" ::: "memory");
    };

    int g = lane >> 3, lr = lane & 7;
    auto compute = [&](int st) {
        unsigned abase = sbase + (st * STAGE) * 2;
        unsigned bbase = abase + ASZ * 2;
        #pragma unroll
        for (int ks = 0; ks < 2; ks++) {
            int k0 = ks * 16;
            unsigned af[2][4];
            #pragma unroll
            for (int mi = 0; mi < 2; mi++) {
                int row = wm * 32 + mi * 16 + (g & 1) * 8 + lr;
                int col = k0 + (g >> 1) * 8;
                ldsm_x4(af[mi][0], af[mi][1], af[mi][2], af[mi][3],
                        abase + (row * ASTR + col) * 2);
            }
            #pragma unroll
            for (int p = 0; p < 2; p++) {
                int row = k0 + (g & 1) * 8 + lr;
                int col = wn * 32 + p * 16 + (g >> 1) * 8;
                unsigned b0, b1, b2, b3;
                ldsm_x4t(b0, b1, b2, b3, bbase + (row * BSTR + col) * 2);
                #pragma unroll
                for (int mi = 0; mi < 2; mi++) {
                    MMA16816(acc[mi][2 * p], af[mi], b0, b1);
                    MMA16816(acc[mi][2 * p + 1], af[mi], b2, b3);
                }
            }
        }
    };

    int nt = Kd / BK;
    issue(0, 0);
    issue(1, BK);
    int st = 0;
    for (int i = 0; i < nt; i++) {
        if (i == nt - 1)
            asm volatile("cp.async.wait_group 0;\n" ::: "memory");
        else
            asm volatile("cp.async.wait_group 1;\n" ::: "memory");
        __syncthreads();
        if (i + 2 < nt) {
            int st2 = st + 2; if (st2 >= 3) st2 -= 3;
            issue(st2, (i + 2) * BK);
        }
        compute(st);
        if (++st == 3) st = 0;
    }

    #pragma unroll
    for (int mi = 0; mi < 2; mi++) {
        int r0 = bm + wm * 32 + mi * 16 + (lane >> 2);
        #pragma unroll
        for (int ni = 0; ni < 4; ni++) {
            int c0 = bn + wn * 32 + ni * 8 + (lane & 3) * 2;
            if (c0 >= N) continue;
            #pragma unroll
            for (int h = 0; h < 2; h++) {
                int rr = r0 + h * 8;
                *reinterpret_cast<float2*>(&Cp[(size_t)rr * N + c0]) =
                    make_float2(acc[mi][ni][h * 2 + 0], acc[mi][ni][h * 2 + 1]);
            }
        }
    }
}

// ---------------------------------------------------------------------------
// Reduces
// ---------------------------------------------------------------------------
__global__ void __launch_bounds__(256) reduce8_k(
    const float* __restrict__ P, const float* __restrict__ bias,
    float* __restrict__ C, __half* __restrict__ Dh)
{
    const size_t PS = (size_t)NROWS * 160;
    size_t i = (size_t)blockIdx.x * 256 + threadIdx.x;
    int col = (int)(i % 160);
    size_t row = i / 160;
    float v = bias[col];
    #pragma unroll
    for (int p = 0; p < 8; p++) v += P[i + p * PS];
    if (col < 128) Dh[row * 128 + col] = __float2half(v);
    else           C[i] = v;
}

__global__ void __launch_bounds__(256) reduce4_out_k(
    const float* __restrict__ P, const float* __restrict__ bias,
    const float* __restrict__ x, float* __restrict__ C)
{
    const size_t PS = (size_t)NROWS * DMv;
    size_t i = ((size_t)blockIdx.x * 256 + threadIdx.x) * 4;
    float4 a = *reinterpret_cast<const float4*>(&P[i]);
    float4 b = *reinterpret_cast<const float4*>(&P[i + PS]);
    float4 c = *reinterpret_cast<const float4*>(&P[i + 2 * PS]);
    float4 d = *reinterpret_cast<const float4*>(&P[i + 3 * PS]);
    float4 r = *reinterpret_cast<const float4*>(&x[i]);
    const float4 bv = *reinterpret_cast<const float4*>(&bias[i % DMv]);
    float4 o;
    o.x = a.x + b.x + c.x + d.x + r.x + bv.x;
    o.y = a.y + b.y + c.y + d.y + r.y + bv.y;
    o.z = a.z + b.z + c.z + d.z + r.z + bv.z;
    o.w = a.w + b.w + c.w + d.w + r.w + bv.w;
    *reinterpret_cast<float4*>(&C[i]) = o;
}

// ---------------------------------------------------------------------------
// Depthwise causal conv (K=4) + SiLU, t-tiled x8.
// Grid (Dv/256, 256): blockIdx.y -> (b, t-group of 8). 11-tap window.
// Reads projH (half), writes x1c (float) + x1cp (half).
// ---------------------------------------------------------------------------
__global__ void __launch_bounds__(256) conv_silu_k(
    const __half* __restrict__ projH, const float* __restrict__ cw,
    const float* __restrict__ cb, float* __restrict__ out, __half* __restrict__ outp)
{
    int d = blockIdx.x * 256 + threadIdx.x;
    int b = blockIdx.y >> 7;
    int t0 = (blockIdx.y & 127) * 8;
    float4 w = *reinterpret_cast<const float4*>(cw + (size_t)d * 4);
    float bias = cb[d];

    const __half* base = projH + (size_t)(b * Tv) * 4096 + d;
    float va[11];
    #pragma unroll
    for (int i = 0; i < 11; i++) {
        int tt = t0 + i - 3;
        va[i] = (tt >= 0) ? __half2float(base[(size_t)tt * 4096]) : 0.f;
    }
    #pragma unroll
    for (int j = 0; j < 8; j++) {
        float acc = bias;
        acc = fmaf(va[j],     w.x, acc);
        acc = fmaf(va[j + 1], w.y, acc);
        acc = fmaf(va[j + 2], w.z, acc);
        acc = fmaf(va[j + 3], w.w, acc);
        float sv = silu_f(acc);
        size_t row = (size_t)(b * Tv + t0 + j);
        out[row * Dv + d] = sv;
        outp[row * Dv + d] = __float2half(sv);
    }
}

// ---------------------------------------------------------------------------
// Selective scan, smem-staged. Gate g read from half proj; ymod half.
// ---------------------------------------------------------------------------
__global__ void __launch_bounds__(256) scan_k(
    const float* __restrict__ dbc, const float* __restrict__ delta,
    const float* __restrict__ x1c, const __half* __restrict__ projH,
    const float* __restrict__ A_log, __half* __restrict__ ymod)
{
    __shared__ float Bs[128][16];
    __shared__ float Cs[128][16];
    __shared__ float De[128][16];
    __shared__ float Xs[128][16];
    __shared__ float Ys[128][16];
    int tid = threadIdx.x;
    int n = tid & 15, grp = tid >> 4;
    int b = blockIdx.y;
    int d0 = blockIdx.x * 16;
    float An = -__expf(A_log[(size_t)(d0 + grp) * NSTv + n]);
    float h = 0.f;

    for (int c = 0; c < 8; c++) {
        __syncthreads();
        int t0 = c * 128;
        for (int idx = tid; idx < 2048; idx += 256) {
            int tl = idx >> 4, nn = idx & 15;
            size_t r = (size_t)(b * Tv + t0 + tl) * 160;
            Bs[tl][nn] = dbc[r + 128 + nn];
            Cs[tl][nn] = dbc[r + 144 + nn];
            size_t rr = (size_t)(b * Tv + t0 + tl) * Dv + d0 + nn;
            De[tl][nn] = delta[rr];
            Xs[tl][nn] = x1c[rr];
        }
        __syncthreads();
        #pragma unroll 8
        for (int tl = 0; tl < 128; tl++) {
            float de = De[tl][grp];
            float xx = Xs[tl][grp];
            float a = __expf(de * An);
            h = fmaf(a, h, de * Bs[tl][n] * xx);
            float p = h * Cs[tl][n];
            p += __shfl_xor_sync(0xffffffffu, p, 8);
            p += __shfl_xor_sync(0xffffffffu, p, 4);
            p += __shfl_xor_sync(0xffffffffu, p, 2);
            p += __shfl_xor_sync(0xffffffffu, p, 1);
            if (n == 0) Ys[tl][grp] = p;
        }
        __syncthreads();
        for (int idx = tid; idx < 2048; idx += 256) {
            int tl = idx >> 4, dl2 = idx & 15;
            int row = b * Tv + t0 + tl;
            float g = __half2float(projH[(size_t)row * 4096 + 2048 + d0 + dl2]);
            ymod[(size_t)row * Dv + d0 + dl2] = __float2half(Ys[tl][dl2] * silu_f(g));
        }
    }
}

// ---------------------------------------------------------------------------
extern "C" void kernel_launch(void* const* d_in, const int* in_sizes, int n_in,
                              void* d_out, int out_size)
{
    const float* x      = (const float*)d_in[0];
    const float* rms_w  = (const float*)d_in[1];
    const float* in_W   = (const float*)d_in[2];
    const float* in_b   = (const float*)d_in[3];
    const float* conv_w = (const float*)d_in[4];
    const float* conv_b = (const float*)d_in[5];
    const float* A_log  = (const float*)d_in[6];
    const float* dbc_W  = (const float*)d_in[7];
    const float* dbc_b  = (const float*)d_in[8];
    const float* dup_W  = (const float*)d_in[9];
    const float* dup_b  = (const float*)d_in[10];
    const float* out_W  = (const float*)d_in[11];
    const float* out_b  = (const float*)d_in[12];
    float* out = (float*)d_out;

    float* S = nullptr;
    cudaGetSymbolAddress((void**)&S, g_scratch);
    __half* Hh    = (__half*)(S + OFF_H);
    __half* ProjH = (__half*)(S + OFF_PROJH);
    __half* X1cp  = (__half*)(S + OFF_X1CP);
    __half* Dh    = (__half*)(S + OFF_DELTAH);
    __half* Ymodh = (__half*)(S + OFF_YMOD);
    __half* Win   = (__half*)(S + OFF_WINR);
    __half* Wdbc  = (__half*)(S + OFF_WDBCR);
    __half* Wdup  = (__half*)(S + OFF_WDUPR);
    __half* Wout  = (__half*)(S + OFF_WOUTR);

    const int SMBIG = 3 * (256 * 40 + 32 * 136) * 2;   // 87552 B
    const int SMMED = 3 * (128 * 40 + 32 * 136) * 2;   // 56832 B
    const int SMDBC = 3 * (128 * 40 + 32 * 72) * 2;    // 44544 B
    cudaFuncSetAttribute(gemm_big<0, __half>, cudaFuncAttributeMaxDynamicSharedMemorySize, SMBIG);
    cudaFuncSetAttribute(gemm_big<3, float>,  cudaFuncAttributeMaxDynamicSharedMemorySize, SMBIG);
    cudaFuncSetAttribute(gemm_med,            cudaFuncAttributeMaxDynamicSharedMemorySize, SMMED);
    cudaFuncSetAttribute(gemm_dbc,            cudaFuncAttributeMaxDynamicSharedMemorySize, SMDBC);

    // 0. Convert all weights to half (one launch)
    convw_k<<<(WSZ1 + WSZ2 + WSZ3 + WSZ4) / 1024, 256>>>(
        in_W, dbc_W, dup_W, out_W, Win, Wdbc, Wdup, Wout);

    // 1. RMSNorm -> h (half)
    rmsnorm_k<<<NROWS, 256>>>(x, rms_w, Hh);

    // 2. in_proj -> ProjH (half)   grid 256
    gemm_big<0, __half><<<dim3(32, 8, 1), 256, SMBIG>>>(
        Hh, Win, in_b, ProjH, 4096, 1024, 1024, 0);

    // 3. depthwise conv + SiLU (t-tiled x8)
    conv_silu_k<<<dim3(Dv / 256, 256), 256>>>(
        ProjH, conv_w, conv_b, S + OFF_X1C, X1cp);

    // 4. dbc: split-K x8 + reduce     grid 384
    gemm_dbc<<<dim3(3, 16, 8), 256, SMDBC>>>(
        X1cp, Wdbc, S + OFF_DBCP, 160, 256, 2048, (size_t)NROWS * 160);
    reduce8_k<<<(NROWS * 160) / 256, 256>>>(S + OFF_DBCP, dbc_b, S + OFF_DBC, Dh);

    // 5. delta up-proj + softplus     grid 256
    gemm_med<<<dim3(16, 16), 256, SMMED>>>(
        Dh, Wdup, dup_b, S + OFF_DELTA, 2048, 128, 128);

    // 6. selective scan + silu(g) gating
    scan_k<<<dim3(Dv / 16, 2), 256>>>(
        S + OFF_DBC, S + OFF_DELTA, S + OFF_X1C, ProjH, A_log, Ymodh);

    // 7. out_proj split-K x4 + fused reduce   grid 256
    gemm_big<3, float><<<dim3(8, 8, 4), 256, SMBIG>>>(
        Ymodh, Wout, nullptr, S + OFF_OUTP, 1024, 512, 2048,
        (size_t)NROWS * DMv);
    reduce4_out_k<<<(NROWS * DMv) / 1024, 256>>>(S + OFF_OUTP, out_b, x, out);
}